// round 8
// baseline (speedup 1.0000x reference)
#include <cuda_runtime.h>
#include <cuda_fp16.h>
#include <math.h>
#include <stdint.h>

#define BATCH 32
#define SEQ   197
#define MTOK  (BATCH*SEQ)
#define HID   768
#define NH    12
#define DH    64
#define INTER 3072
#define NLAYER 12
#define NCLS  1000
#define GP    14
#define PSZ   16
#define IMG   224
#define MPATCH (BATCH*GP*GP)
#define QKVW  2304
typedef __half fp16;

__device__ float g_h  [MTOK*HID];
__device__ float g_qkv[MTOK*QKVW];
__device__ fp16 g_hn_h[MTOK*HID];
__device__ fp16 g_hn_l[MTOK*HID];
__device__ fp16 g_at_h[MTOK*HID];
__device__ fp16 g_at_l[MTOK*HID];
__device__ fp16 g_m1_h[MTOK*INTER];
__device__ fp16 g_m1_l[MTOK*INTER];
__device__ fp16 g_xp_h[MPATCH*HID];
__device__ fp16 g_xp_l[MPATCH*HID];
__device__ fp16 g_Wq_h[NLAYER*QKVW*HID];
__device__ fp16 g_Wo_h[NLAYER*HID*HID];
__device__ fp16 g_W1_h[NLAYER*INTER*HID];
__device__ fp16 g_W2_h[NLAYER*HID*INTER];
__device__ fp16 g_Wp_h[HID*HID];
__device__ float g_bq[NLAYER*QKVW];

__device__ __forceinline__ uint32_t smem_u32(const void* p){
    uint32_t a; asm("{ .reg .u64 t; cvta.to.shared.u64 t, %1; cvt.u32.u64 %0, t; }":"=r"(a):"l"(p)); return a;
}

#define LDM4(r, ad) asm volatile("ldmatrix.sync.aligned.m8n8.x4.shared.b16 {%0,%1,%2,%3}, [%4];" \
  : "=r"((r)[0]),"=r"((r)[1]),"=r"((r)[2]),"=r"((r)[3]) : "r"(ad))
#define MMA(d, a, b0, b1) asm volatile( \
  "mma.sync.aligned.m16n8k16.row.col.f32.f16.f16.f32 {%0,%1,%2,%3}, {%4,%5,%6,%7}, {%8,%9}, {%0,%1,%2,%3};" \
  : "+f"((d)[0]), "+f"((d)[1]), "+f"((d)[2]), "+f"((d)[3]) \
  : "r"((a)[0]), "r"((a)[1]), "r"((a)[2]), "r"((a)[3]), "r"(b0), "r"(b1))
__device__ __forceinline__ void cpa16(uint32_t dst, const void* src, bool pred){
    asm volatile("cp.async.cg.shared.global [%0], [%1], 16, %2;" :: "r"(dst), "l"(src), "r"(pred?16:0));
}
#define CPA_COMMIT() asm volatile("cp.async.commit_group;" ::: "memory")
#define CPA_WAIT1()  asm volatile("cp.async.wait_group 1;" ::: "memory")
#define CPA_WAIT0()  asm volatile("cp.async.wait_group 0;" ::: "memory")

// ---- fp16 2-MMA split GEMM: C[M,N] = (Ah+Al)[M,K] @ Bh[N,K]^T, fp32 accum ----
// 128x128 block tile, 4 warps, warp tile 64x64, BK=32, 3-stage cp.async.
#define BM 128
#define BN 128
#define BK 32
#define SSTR 24576          // per-stage: Ah 8K | Al 8K | Bh 8K
#define GSMEM 73728         // 3 stages; epilogue (67.6KB) reuses it
#define NTHR 128

__device__ __forceinline__ void load_stage(
    uint32_t d, const fp16* __restrict__ Ah, const fp16* __restrict__ Al,
    const fp16* __restrict__ Bh,
    int M, int K, int m0, int n0, int k0, int tid)
{
    const int lc = tid & 3;
    #pragma unroll
    for (int p = 0; p < 4; p++) {
        const int lr = (tid >> 2) + p*32;
        const uint32_t sw = (uint32_t)(lr*64 + ((lc ^ ((lr>>1)&3))<<4));
        const bool aok = (m0 + lr) < M;
        const size_t ag = (size_t)(m0 + lr)*K + k0 + lc*8;
        const size_t bg = (size_t)(n0 + lr)*K + k0 + lc*8;
        cpa16(d + sw,         Ah + ag, aok);
        cpa16(d + 8192 + sw,  Al + ag, aok);
        cpa16(d + 16384 + sw, Bh + bg, true);
    }
}

__global__ __launch_bounds__(NTHR,2) void tc_gemm(
    const fp16* __restrict__ Ah, const fp16* __restrict__ Al,
    const fp16* __restrict__ Bh,
    int M, int N, int K, const float* __restrict__ bias, const float* __restrict__ resid,
    float* __restrict__ Cf, fp16* __restrict__ Chi, fp16* __restrict__ Clo, int act)
{
    extern __shared__ char smc[];
    const uint32_t sb = smem_u32(smc);
    const int tid = threadIdx.x, wid = tid>>5, lane = tid&31;
    const int m0 = blockIdx.y*BM, n0 = blockIdx.x*BN;
    const int warp_m = wid & 1, warp_n = wid >> 1;

    const int nc = K / BK;
    #pragma unroll
    for (int s = 0; s < 2; s++) {
        load_stage(sb + s*SSTR, Ah, Al, Bh, M, K, m0, n0, s*BK, tid);
        CPA_COMMIT();
    }

    float acc[4][8][4];
    #pragma unroll
    for (int i=0;i<4;i++)
        #pragma unroll
        for (int j=0;j<8;j++)
            #pragma unroll
            for (int t=0;t<4;t++) acc[i][j][t]=0.f;

    const int lrow8 = (lane&7) + ((lane>>3)&1)*8;
    const int lhalf = lane>>4;

    for (int c = 0; c < nc; c++) {
        const int sidx = c % 3;
        CPA_WAIT1();
        __syncthreads();
        if (c + 2 < nc) {
            load_stage(sb + ((c+2)%3)*SSTR, Ah, Al, Bh, M, K, m0, n0, (c+2)*BK, tid);
            CPA_COMMIT();
        }
        const uint32_t sa = sb + sidx*SSTR;
        #pragma unroll
        for (int kk = 0; kk < 2; kk++) {
            const int c16 = kk*2 + lhalf;
            uint32_t ah[4][4], al[4][4];
            #pragma unroll
            for (int mt = 0; mt < 4; mt++) {
                int row = warp_m*64 + mt*16 + lrow8;
                uint32_t ad = sa + (uint32_t)(row*64 + ((c16 ^ ((row>>1)&3))<<4));
                LDM4(ah[mt], ad);
                LDM4(al[mt], ad + 8192);
            }
            #pragma unroll
            for (int n4 = 0; n4 < 4; n4++) {
                int row = warp_n*64 + n4*16 + lrow8;
                uint32_t bd = sa + 16384 + (uint32_t)(row*64 + ((c16 ^ ((row>>1)&3))<<4));
                uint32_t bh[4];
                LDM4(bh, bd);
                // 8 independent Ah-MMAs (distinct accumulators), then 8 Al-MMAs:
                // breaks the per-acc RAW chain of the paired ordering.
                #pragma unroll
                for (int od = 0; od < 2; od++)
                    #pragma unroll
                    for (int mt = 0; mt < 4; mt++)
                        MMA(acc[mt][n4*2+od], ah[mt], bh[od], bh[od+2]);
                #pragma unroll
                for (int od = 0; od < 2; od++)
                    #pragma unroll
                    for (int mt = 0; mt < 4; mt++)
                        MMA(acc[mt][n4*2+od], al[mt], bh[od], bh[od+2]);
            }
        }
    }
    CPA_WAIT0();
    __syncthreads();

    // epilogue: acc -> smem (stride 132) -> coalesced global
    float* stg = (float*)smc;
    const int ST = 132;
    #pragma unroll
    for (int mt = 0; mt < 4; mt++)
        #pragma unroll
        for (int nt = 0; nt < 8; nt++)
            #pragma unroll
            for (int i = 0; i < 4; i++) {
                int row = warp_m*64 + mt*16 + (lane>>2) + (i>>1)*8;
                int col = warp_n*64 + nt*8 + 2*(lane&3) + (i&1);
                stg[row*ST + col] = acc[mt][nt][i];
            }
    __syncthreads();

    #pragma unroll
    for (int i = 0; i < 32; i++) {
        int g = tid + i*NTHR;           // 128 rows x 32 quads
        int r = g >> 5, q = g & 31;
        int gm = m0 + r;
        if (gm >= M) continue;
        int n = n0 + q*4;
        float v0 = stg[r*ST + q*4 + 0] + bias[n+0];
        float v1 = stg[r*ST + q*4 + 1] + bias[n+1];
        float v2 = stg[r*ST + q*4 + 2] + bias[n+2];
        float v3 = stg[r*ST + q*4 + 3] + bias[n+3];
        if (act) {
            v0 = 0.5f*v0*(1.0f+erff(v0*0.70710678118654752f));
            v1 = 0.5f*v1*(1.0f+erff(v1*0.70710678118654752f));
            v2 = 0.5f*v2*(1.0f+erff(v2*0.70710678118654752f));
            v3 = 0.5f*v3*(1.0f+erff(v3*0.70710678118654752f));
        }
        if (resid) {
            const float* rp = resid + (size_t)gm*N + n;
            v0 += rp[0]; v1 += rp[1]; v2 += rp[2]; v3 += rp[3];
        }
        if (Cf) {
            *(float4*)(Cf + (size_t)gm*N + n) = make_float4(v0,v1,v2,v3);
        } else {
            fp16 h0=__float2half(v0),h1=__float2half(v1),h2=__float2half(v2),h3=__float2half(v3);
            fp16 l0=__float2half(v0-__half2float(h0)),l1=__float2half(v1-__half2float(h1));
            fp16 l2=__float2half(v2-__half2float(h2)),l3=__float2half(v3-__half2float(h3));
            uint2 sh,sl;
            sh.x=(uint32_t)__half_as_ushort(h0)|((uint32_t)__half_as_ushort(h1)<<16);
            sh.y=(uint32_t)__half_as_ushort(h2)|((uint32_t)__half_as_ushort(h3)<<16);
            sl.x=(uint32_t)__half_as_ushort(l0)|((uint32_t)__half_as_ushort(l1)<<16);
            sl.y=(uint32_t)__half_as_ushort(l2)|((uint32_t)__half_as_ushort(l3)<<16);
            *(uint2*)(Chi+(size_t)gm*N+n)=sh; *(uint2*)(Clo+(size_t)gm*N+n)=sl;
        }
    }
}

// ---- weight conversions (hi fp16 only) ----
__global__ void convT_k(const float* __restrict__ in, fp16* __restrict__ hi, int K, int N){
    __shared__ float t[32][33];
    int l=blockIdx.z; in+=(size_t)l*K*N; hi+=(size_t)l*N*K;
    int n0=blockIdx.x*32, k0=blockIdx.y*32, tx=threadIdx.x, ty=threadIdx.y;
    #pragma unroll
    for (int i=0;i<32;i+=8) t[ty+i][tx]=in[(size_t)(k0+ty+i)*N+n0+tx];
    __syncthreads();
    #pragma unroll
    for (int i=0;i<32;i+=8)
        hi[(size_t)(n0+ty+i)*K+k0+tx]=__float2half(t[tx][ty+i]);
}
__global__ void convQKV_k(const float* __restrict__ wq, const float* __restrict__ wk, const float* __restrict__ wv,
                          fp16* __restrict__ hi){
    __shared__ float t[32][33];
    int l=blockIdx.z, k0=blockIdx.x*32, n0=blockIdx.y*32;
    int sel=n0/HID, nn=n0%HID, hh=nn/DH, d0=nn%DH;
    const float* w=(sel==0)?wq:(sel==1)?wk:wv;
    const float* base=w+((size_t)l*NH+hh)*HID*DH;
    int tx=threadIdx.x, ty=threadIdx.y;
    #pragma unroll
    for (int i=0;i<32;i+=8) t[ty+i][tx]=base[(size_t)(k0+ty+i)*DH+d0+tx];
    __syncthreads();
    size_t ob=(size_t)l*QKVW+n0;
    #pragma unroll
    for (int i=0;i<32;i+=8)
        hi[(ob+ty+i)*HID+k0+tx]=__float2half(t[tx][ty+i]);
}
__global__ void convWP_k(const float* __restrict__ w, fp16* __restrict__ hi){
    int i=blockIdx.x*blockDim.x+threadIdx.x; if (i>=HID*HID) return;
    hi[i]=__float2half(w[i]);
}
__global__ void cbias_k(const float* __restrict__ bq, const float* __restrict__ bk, const float* __restrict__ bv, float* __restrict__ o){
    int i=blockIdx.x*blockDim.x+threadIdx.x; if (i>=NLAYER*QKVW) return;
    int l=i/QKVW, n=i%QKVW;
    o[i] = (n<HID)? bq[l*HID+n] : (n<2*HID)? bk[l*HID+n-HID] : bv[l*HID+n-2*HID];
}

// ---- elementwise kernels ----
__global__ void patchify(const float* __restrict__ x, fp16* __restrict__ hi, fp16* __restrict__ lo){
    int idx=blockIdx.x*blockDim.x+threadIdx.x; if (idx>=MPATCH*HID) return;
    int m=idx/HID, kk=idx%HID, b=m/(GP*GP), r=m%(GP*GP), i=r/GP, j=r%GP;
    int c=kk/(PSZ*PSZ), rem=kk%(PSZ*PSZ), p=rem/PSZ, q=rem%PSZ;
    float v=x[((size_t)(b*3+c)*IMG+(i*PSZ+p))*IMG+(j*PSZ+q)];
    fp16 h=__float2half(v);
    hi[idx]=h; lo[idx]=__float2half(v-__half2float(h));
}
__global__ void build_h(const float* __restrict__ xe, const float* __restrict__ cls,
                        const float* __restrict__ pos, float* __restrict__ h){
    int idx=blockIdx.x*blockDim.x+threadIdx.x; if (idx>=MTOK*HID) return;
    int m=idx/HID, d=idx%HID, b=m/SEQ, s=m%SEQ;
    float pv=pos[s*HID+d];
    h[idx] = (s==0)? cls[d]+pv : xe[(size_t)(b*(GP*GP)+(s-1))*HID+d]+pv;
}
__global__ void layernorm_k(const float* __restrict__ x, const float* __restrict__ sc,
                            const float* __restrict__ bi, fp16* __restrict__ oh, fp16* __restrict__ ol){
    int m=blockIdx.x, tid=threadIdx.x;
    const float* row=x+(size_t)m*HID;
    float v0=row[tid], v1=row[tid+256], v2=row[tid+512];
    __shared__ float red[256];
    red[tid]=v0+v1+v2; __syncthreads();
    #pragma unroll
    for (int o=128;o>0;o>>=1){ if(tid<o) red[tid]+=red[tid+o]; __syncthreads(); }
    float mu=red[0]*(1.0f/768.0f); __syncthreads();
    float d0=v0-mu,d1=v1-mu,d2=v2-mu;
    red[tid]=d0*d0+d1*d1+d2*d2; __syncthreads();
    #pragma unroll
    for (int o=128;o>0;o>>=1){ if(tid<o) red[tid]+=red[tid+o]; __syncthreads(); }
    float rs=rsqrtf(red[0]*(1.0f/768.0f)+1e-5f);
    size_t base=(size_t)m*HID;
    #pragma unroll
    for (int j=0;j<3;j++){
        int col=tid+j*256;
        float dd=(j==0)?d0:(j==1)?d1:d2;
        float v=dd*rs*sc[col]+bi[col];
        fp16 h=__float2half(v);
        oh[base+col]=h; ol[base+col]=__float2half(v-__half2float(h));
    }
}

// ---- attention (fp32, fused qkv input, fp16-split output) ----
#define ATT_SMEMF (197*65*2 + 8*200 + 8*64)
__global__ __launch_bounds__(256) void attention_k(const float* __restrict__ qkv, fp16* __restrict__ oh, fp16* __restrict__ ol){
    extern __shared__ float s[];
    float* Kh=s; float* Vh=s+197*65; float* sr=Vh+197*65; float* qr=sr+8*200;
    int bh=blockIdx.x, b=bh/NH, h=bh%NH;
    int tid=threadIdx.x, wid=tid>>5, lane=tid&31;
    const float* kb=qkv+(size_t)(b*SEQ)*QKVW+HID+h*DH;
    const float* vb=qkv+(size_t)(b*SEQ)*QKVW+2*HID+h*DH;
    for (int idx=tid; idx<SEQ*DH; idx+=256){
        int t=idx>>6, dk=idx&63;
        Kh[t*65+dk]=kb[(size_t)t*QKVW+dk];
        Vh[t*65+dk]=vb[(size_t)t*QKVW+dk];
    }
    __syncthreads();
    const float* qb=qkv+(size_t)(b*SEQ)*QKVW+h*DH;
    size_t ob=(size_t)(b*SEQ)*HID+h*DH;
    float* myS=sr+wid*200; float* myQ=qr+wid*64;
    for (int sq=wid; sq<SEQ; sq+=8){
        myQ[lane]=qb[(size_t)sq*QKVW+lane];
        myQ[lane+32]=qb[(size_t)sq*QKVW+lane+32];
        __syncwarp();
        float scs[7], mx=-1e30f;
        #pragma unroll
        for (int i=0;i<7;i++){
            int t=lane+32*i; float d=-1e30f;
            if (t<SEQ){ d=0.f;
                #pragma unroll
                for (int dk=0;dk<64;dk++) d+=myQ[dk]*Kh[t*65+dk];
                d*=0.125f; }
            scs[i]=d; mx=fmaxf(mx,d);
        }
        #pragma unroll
        for (int o=16;o>0;o>>=1) mx=fmaxf(mx,__shfl_xor_sync(0xffffffffu,mx,o));
        float sum=0.f;
        #pragma unroll
        for (int i=0;i<7;i++){ int t=lane+32*i; float e=(t<SEQ)?expf(scs[i]-mx):0.f; scs[i]=e; sum+=e; }
        #pragma unroll
        for (int o=16;o>0;o>>=1) sum+=__shfl_xor_sync(0xffffffffu,sum,o);
        float inv=1.f/sum;
        #pragma unroll
        for (int i=0;i<7;i++){ int t=lane+32*i; if (t<SEQ) myS[t]=scs[i]*inv; }
        __syncwarp();
        float a0=0.f, a1=0.f;
        for (int t=0;t<SEQ;t++){ float p=myS[t]; a0+=p*Vh[t*65+lane]; a1+=p*Vh[t*65+lane+32]; }
        size_t o0=ob+(size_t)sq*HID+lane;
        fp16 h0=__float2half(a0), h1=__float2half(a1);
        oh[o0]=h0; oh[o0+32]=h1;
        ol[o0]=__float2half(a0-__half2float(h0));
        ol[o0+32]=__float2half(a1-__half2float(h1));
        __syncwarp();
    }
}

__global__ void head_k(const float* __restrict__ h, const float* __restrict__ W,
                       const float* __restrict__ bi, float* __restrict__ out){
    __shared__ float row[HID];
    int b=blockIdx.y, n=blockIdx.x*256+threadIdx.x;
    const float* hr=h+(size_t)(b*SEQ)*HID;
    for (int i=threadIdx.x;i<HID;i+=256) row[i]=hr[i];
    __syncthreads();
    if (n<NCLS){
        float acc=bi[n];
        for (int d=0;d<HID;d++) acc+=row[d]*W[(size_t)d*NCLS+n];
        out[(size_t)b*NCLS+n]=acc;
    }
}

template<typename T> static T* sym(const void* s){ void* p=nullptr; cudaGetSymbolAddress(&p,s); return (T*)p; }

extern "C" void kernel_launch(void* const* d_in, const int* in_sizes, int n_in, void* d_out, int out_size){
    const float *x=(const float*)d_in[0], *conv_w=(const float*)d_in[1], *conv_b=(const float*)d_in[2];
    const float *cls=(const float*)d_in[3], *pos=(const float*)d_in[4];
    const float *ln1_s=(const float*)d_in[5], *ln1_b=(const float*)d_in[6];
    const float *wq=(const float*)d_in[7], *bq=(const float*)d_in[8];
    const float *wk=(const float*)d_in[9], *bk=(const float*)d_in[10];
    const float *wv=(const float*)d_in[11], *bv=(const float*)d_in[12];
    const float *wo=(const float*)d_in[13], *bo=(const float*)d_in[14];
    const float *ln2_s=(const float*)d_in[15], *ln2_b=(const float*)d_in[16];
    const float *w1=(const float*)d_in[17], *b1=(const float*)d_in[18];
    const float *w2=(const float*)d_in[19], *b2=(const float*)d_in[20];
    const float *head_w=(const float*)d_in[21], *head_b=(const float*)d_in[22];
    float* out=(float*)d_out;

    float* h_  = sym<float>(g_h);
    float* qkv_= sym<float>(g_qkv);
    float* bq_ = sym<float>(g_bq);
    fp16 *hnh=sym<fp16>(g_hn_h), *hnl=sym<fp16>(g_hn_l);
    fp16 *ath=sym<fp16>(g_at_h), *atl=sym<fp16>(g_at_l);
    fp16 *m1h=sym<fp16>(g_m1_h), *m1l=sym<fp16>(g_m1_l);
    fp16 *xph=sym<fp16>(g_xp_h), *xpl=sym<fp16>(g_xp_l);
    fp16 *Wqh=sym<fp16>(g_Wq_h);
    fp16 *Woh=sym<fp16>(g_Wo_h);
    fp16 *W1h=sym<fp16>(g_W1_h);
    fp16 *W2h=sym<fp16>(g_W2_h);
    fp16 *Wph=sym<fp16>(g_Wp_h);

    cudaFuncSetAttribute(tc_gemm, cudaFuncAttributeMaxDynamicSharedMemorySize, GSMEM);
    cudaFuncSetAttribute(attention_k, cudaFuncAttributeMaxDynamicSharedMemorySize, ATT_SMEMF*(int)sizeof(float));

    dim3 tb(32,8);
    patchify<<<(MPATCH*HID+255)/256,256>>>(x, xph, xpl);
    convWP_k<<<(HID*HID+255)/256,256>>>(conv_w, Wph);
    cbias_k<<<(NLAYER*QKVW+255)/256,256>>>(bq,bk,bv,bq_);
    tc_gemm<<<dim3(HID/BN,(MPATCH+BM-1)/BM),NTHR,GSMEM>>>(xph,xpl,Wph,MPATCH,HID,HID,conv_b,nullptr,qkv_,nullptr,nullptr,0);
    convQKV_k<<<dim3(24,72,12),tb>>>(wq,wk,wv,Wqh);
    convT_k<<<dim3(24,24,12),tb>>>(wo, Woh, HID, HID);
    convT_k<<<dim3(96,24,12),tb>>>(w1, W1h, HID, INTER);
    convT_k<<<dim3(24,96,12),tb>>>(w2, W2h, INTER, HID);
    build_h<<<(MTOK*HID+255)/256,256>>>(qkv_, cls, pos, h_);

    const int MT=(MTOK+BM-1)/BM;
    for (int l=0;l<NLAYER;l++){
        layernorm_k<<<MTOK,256>>>(h_, ln1_s+l*HID, ln1_b+l*HID, hnh, hnl);
        tc_gemm<<<dim3(QKVW/BN,MT),NTHR,GSMEM>>>(hnh,hnl,Wqh+(size_t)l*QKVW*HID,MTOK,QKVW,HID,bq_+l*QKVW,nullptr,qkv_,nullptr,nullptr,0);
        attention_k<<<BATCH*NH,256,ATT_SMEMF*(int)sizeof(float)>>>(qkv_, ath, atl);
        tc_gemm<<<dim3(HID/BN,MT),NTHR,GSMEM>>>(ath,atl,Woh+(size_t)l*HID*HID,MTOK,HID,HID,bo+l*HID,h_,h_,nullptr,nullptr,0);
        layernorm_k<<<MTOK,256>>>(h_, ln2_s+l*HID, ln2_b+l*HID, hnh, hnl);
        tc_gemm<<<dim3(INTER/BN,MT),NTHR,GSMEM>>>(hnh,hnl,W1h+(size_t)l*INTER*HID,MTOK,INTER,HID,b1+l*INTER,nullptr,nullptr,m1h,m1l,1);
        tc_gemm<<<dim3(HID/BN,MT),NTHR,GSMEM>>>(m1h,m1l,W2h+(size_t)l*HID*INTER,MTOK,HID,INTER,b2+l*HID,h_,h_,nullptr,nullptr,0);
    }
    head_k<<<dim3((NCLS+255)/256,BATCH),256>>>(h_, head_w, head_b, out);
}

// round 9
// speedup vs baseline: 1.0975x; 1.0975x over previous
#include <cuda_runtime.h>
#include <cuda_fp16.h>
#include <math.h>
#include <stdint.h>

#define BATCH 32
#define SEQ   197
#define MTOK  (BATCH*SEQ)
#define HID   768
#define NH    12
#define DH    64
#define INTER 3072
#define NLAYER 12
#define NCLS  1000
#define GP    14
#define PSZ   16
#define IMG   224
#define MPATCH (BATCH*GP*GP)
#define QKVW  2304
typedef __half fp16;

__device__ float g_h  [MTOK*HID];
__device__ float g_qkv[MTOK*QKVW];
__device__ fp16 g_hn_h[MTOK*HID];
__device__ fp16 g_hn_l[MTOK*HID];
__device__ fp16 g_at_h[MTOK*HID];
__device__ fp16 g_at_l[MTOK*HID];
__device__ fp16 g_m1_h[MTOK*INTER];
__device__ fp16 g_m1_l[MTOK*INTER];
__device__ fp16 g_xp_h[MPATCH*HID];
__device__ fp16 g_xp_l[MPATCH*HID];
__device__ fp16 g_Wq_h[NLAYER*QKVW*HID];
__device__ fp16 g_Wo_h[NLAYER*HID*HID];
__device__ fp16 g_W1_h[NLAYER*INTER*HID];
__device__ fp16 g_W2_h[NLAYER*HID*INTER];
__device__ fp16 g_Wp_h[HID*HID];
__device__ float g_bq[NLAYER*QKVW];

__device__ __forceinline__ uint32_t smem_u32(const void* p){
    uint32_t a; asm("{ .reg .u64 t; cvta.to.shared.u64 t, %1; cvt.u32.u64 %0, t; }":"=r"(a):"l"(p)); return a;
}

#define LDM4(r, ad) asm volatile("ldmatrix.sync.aligned.m8n8.x4.shared.b16 {%0,%1,%2,%3}, [%4];" \
  : "=r"((r)[0]),"=r"((r)[1]),"=r"((r)[2]),"=r"((r)[3]) : "r"(ad))
#define MMA(d, a, b0, b1) asm volatile( \
  "mma.sync.aligned.m16n8k16.row.col.f32.f16.f16.f32 {%0,%1,%2,%3}, {%4,%5,%6,%7}, {%8,%9}, {%0,%1,%2,%3};" \
  : "+f"((d)[0]), "+f"((d)[1]), "+f"((d)[2]), "+f"((d)[3]) \
  : "r"((a)[0]), "r"((a)[1]), "r"((a)[2]), "r"((a)[3]), "r"(b0), "r"(b1))
__device__ __forceinline__ void cpa16(uint32_t dst, const void* src, bool pred){
    asm volatile("cp.async.cg.shared.global [%0], [%1], 16, %2;" :: "r"(dst), "l"(src), "r"(pred?16:0));
}
#define CPA_COMMIT() asm volatile("cp.async.commit_group;" ::: "memory")
#define CPA_WAIT1()  asm volatile("cp.async.wait_group 1;" ::: "memory")
#define CPA_WAIT0()  asm volatile("cp.async.wait_group 0;" ::: "memory")

// ---- fp16 2-MMA split GEMM: C[M,N] = (Ah+Al)[M,K] @ Bh[N,K]^T, fp32 accum ----
// 128x128 block tile, 8 warps (warp tile 32x64), BK=32, 3-stage cp.async.
// 256 threads, <=128 regs -> 2 CTA/SM = 16 warps/SM for latency hiding.
#define BM 128
#define BN 128
#define BK 32
#define SSTR 24576          // per-stage: Ah 8K | Al 8K | Bh 8K
#define GSMEM 73728         // 3 stages; epilogue (67.6KB) reuses it
#define NTHR 256

__device__ __forceinline__ void load_stage(
    uint32_t d, const fp16* __restrict__ Ah, const fp16* __restrict__ Al,
    const fp16* __restrict__ Bh,
    int M, int K, int m0, int n0, int k0, int tid)
{
    const int lc = tid & 3;
    #pragma unroll
    for (int p = 0; p < 2; p++) {
        const int lr = (tid >> 2) + p*64;
        const uint32_t sw = (uint32_t)(lr*64 + ((lc ^ ((lr>>1)&3))<<4));
        const bool aok = (m0 + lr) < M;
        const size_t ag = (size_t)(m0 + lr)*K + k0 + lc*8;
        const size_t bg = (size_t)(n0 + lr)*K + k0 + lc*8;
        cpa16(d + sw,         Ah + ag, aok);
        cpa16(d + 8192 + sw,  Al + ag, aok);
        cpa16(d + 16384 + sw, Bh + bg, true);
    }
}

__global__ __launch_bounds__(NTHR,2) void tc_gemm(
    const fp16* __restrict__ Ah, const fp16* __restrict__ Al,
    const fp16* __restrict__ Bh,
    int M, int N, int K, const float* __restrict__ bias, const float* __restrict__ resid,
    float* __restrict__ Cf, fp16* __restrict__ Chi, fp16* __restrict__ Clo, int act)
{
    extern __shared__ char smc[];
    const uint32_t sb = smem_u32(smc);
    const int tid = threadIdx.x, wid = tid>>5, lane = tid&31;
    const int m0 = blockIdx.y*BM, n0 = blockIdx.x*BN;
    const int warp_m = wid & 3, warp_n = wid >> 2;   // 4 x 2 warp grid, tile 32x64

    const int nc = K / BK;
    #pragma unroll
    for (int s = 0; s < 2; s++) {
        load_stage(sb + s*SSTR, Ah, Al, Bh, M, K, m0, n0, s*BK, tid);
        CPA_COMMIT();
    }

    float acc[2][8][4];
    #pragma unroll
    for (int i=0;i<2;i++)
        #pragma unroll
        for (int j=0;j<8;j++)
            #pragma unroll
            for (int t=0;t<4;t++) acc[i][j][t]=0.f;

    const int lrow8 = (lane&7) + ((lane>>3)&1)*8;
    const int lhalf = lane>>4;

    for (int c = 0; c < nc; c++) {
        const int sidx = c % 3;
        CPA_WAIT1();
        __syncthreads();
        if (c + 2 < nc) {
            load_stage(sb + ((c+2)%3)*SSTR, Ah, Al, Bh, M, K, m0, n0, (c+2)*BK, tid);
            CPA_COMMIT();
        }
        const uint32_t sa = sb + sidx*SSTR;
        #pragma unroll
        for (int kk = 0; kk < 2; kk++) {
            const int c16 = kk*2 + lhalf;
            uint32_t ah[2][4], al[2][4];
            #pragma unroll
            for (int mt = 0; mt < 2; mt++) {
                int row = warp_m*32 + mt*16 + lrow8;
                uint32_t ad = sa + (uint32_t)(row*64 + ((c16 ^ ((row>>1)&3))<<4));
                LDM4(ah[mt], ad);
                LDM4(al[mt], ad + 8192);
            }
            #pragma unroll
            for (int n4 = 0; n4 < 4; n4++) {
                int row = warp_n*64 + n4*16 + lrow8;
                uint32_t bd = sa + 16384 + (uint32_t)(row*64 + ((c16 ^ ((row>>1)&3))<<4));
                uint32_t bh[4];
                LDM4(bh, bd);
                #pragma unroll
                for (int mt = 0; mt < 2; mt++)
                    #pragma unroll
                    for (int od = 0; od < 2; od++) {
                        const int nt = n4*2 + od;
                        MMA(acc[mt][nt], ah[mt], bh[od], bh[od+2]);
                        MMA(acc[mt][nt], al[mt], bh[od], bh[od+2]);
                    }
            }
        }
    }
    CPA_WAIT0();
    __syncthreads();

    // epilogue: acc -> smem (stride 132) -> coalesced global
    float* stg = (float*)smc;
    const int ST = 132;
    #pragma unroll
    for (int mt = 0; mt < 2; mt++)
        #pragma unroll
        for (int nt = 0; nt < 8; nt++)
            #pragma unroll
            for (int i = 0; i < 4; i++) {
                int row = warp_m*32 + mt*16 + (lane>>2) + (i>>1)*8;
                int col = warp_n*64 + nt*8 + 2*(lane&3) + (i&1);
                stg[row*ST + col] = acc[mt][nt][i];
            }
    __syncthreads();

    #pragma unroll
    for (int i = 0; i < 16; i++) {
        int g = tid + i*NTHR;           // 128 rows x 32 quads
        int r = g >> 5, q = g & 31;
        int gm = m0 + r;
        if (gm >= M) continue;
        int n = n0 + q*4;
        float v0 = stg[r*ST + q*4 + 0] + bias[n+0];
        float v1 = stg[r*ST + q*4 + 1] + bias[n+1];
        float v2 = stg[r*ST + q*4 + 2] + bias[n+2];
        float v3 = stg[r*ST + q*4 + 3] + bias[n+3];
        if (act) {
            v0 = 0.5f*v0*(1.0f+erff(v0*0.70710678118654752f));
            v1 = 0.5f*v1*(1.0f+erff(v1*0.70710678118654752f));
            v2 = 0.5f*v2*(1.0f+erff(v2*0.70710678118654752f));
            v3 = 0.5f*v3*(1.0f+erff(v3*0.70710678118654752f));
        }
        if (resid) {
            const float* rp = resid + (size_t)gm*N + n;
            v0 += rp[0]; v1 += rp[1]; v2 += rp[2]; v3 += rp[3];
        }
        if (Cf) {
            *(float4*)(Cf + (size_t)gm*N + n) = make_float4(v0,v1,v2,v3);
        } else {
            fp16 h0=__float2half(v0),h1=__float2half(v1),h2=__float2half(v2),h3=__float2half(v3);
            fp16 l0=__float2half(v0-__half2float(h0)),l1=__float2half(v1-__half2float(h1));
            fp16 l2=__float2half(v2-__half2float(h2)),l3=__float2half(v3-__half2float(h3));
            uint2 sh,sl;
            sh.x=(uint32_t)__half_as_ushort(h0)|((uint32_t)__half_as_ushort(h1)<<16);
            sh.y=(uint32_t)__half_as_ushort(h2)|((uint32_t)__half_as_ushort(h3)<<16);
            sl.x=(uint32_t)__half_as_ushort(l0)|((uint32_t)__half_as_ushort(l1)<<16);
            sl.y=(uint32_t)__half_as_ushort(l2)|((uint32_t)__half_as_ushort(l3)<<16);
            *(uint2*)(Chi+(size_t)gm*N+n)=sh; *(uint2*)(Clo+(size_t)gm*N+n)=sl;
        }
    }
}

// ---- weight conversions (hi fp16 only) ----
__global__ void convT_k(const float* __restrict__ in, fp16* __restrict__ hi, int K, int N){
    __shared__ float t[32][33];
    int l=blockIdx.z; in+=(size_t)l*K*N; hi+=(size_t)l*N*K;
    int n0=blockIdx.x*32, k0=blockIdx.y*32, tx=threadIdx.x, ty=threadIdx.y;
    #pragma unroll
    for (int i=0;i<32;i+=8) t[ty+i][tx]=in[(size_t)(k0+ty+i)*N+n0+tx];
    __syncthreads();
    #pragma unroll
    for (int i=0;i<32;i+=8)
        hi[(size_t)(n0+ty+i)*K+k0+tx]=__float2half(t[tx][ty+i]);
}
__global__ void convQKV_k(const float* __restrict__ wq, const float* __restrict__ wk, const float* __restrict__ wv,
                          fp16* __restrict__ hi){
    __shared__ float t[32][33];
    int l=blockIdx.z, k0=blockIdx.x*32, n0=blockIdx.y*32;
    int sel=n0/HID, nn=n0%HID, hh=nn/DH, d0=nn%DH;
    const float* w=(sel==0)?wq:(sel==1)?wk:wv;
    const float* base=w+((size_t)l*NH+hh)*HID*DH;
    int tx=threadIdx.x, ty=threadIdx.y;
    #pragma unroll
    for (int i=0;i<32;i+=8) t[ty+i][tx]=base[(size_t)(k0+ty+i)*DH+d0+tx];
    __syncthreads();
    size_t ob=(size_t)l*QKVW+n0;
    #pragma unroll
    for (int i=0;i<32;i+=8)
        hi[(ob+ty+i)*HID+k0+tx]=__float2half(t[tx][ty+i]);
}
__global__ void convWP_k(const float* __restrict__ w, fp16* __restrict__ hi){
    int i=blockIdx.x*blockDim.x+threadIdx.x; if (i>=HID*HID) return;
    hi[i]=__float2half(w[i]);
}
__global__ void cbias_k(const float* __restrict__ bq, const float* __restrict__ bk, const float* __restrict__ bv, float* __restrict__ o){
    int i=blockIdx.x*blockDim.x+threadIdx.x; if (i>=NLAYER*QKVW) return;
    int l=i/QKVW, n=i%QKVW;
    o[i] = (n<HID)? bq[l*HID+n] : (n<2*HID)? bk[l*HID+n-HID] : bv[l*HID+n-2*HID];
}

// ---- elementwise kernels ----
__global__ void patchify(const float* __restrict__ x, fp16* __restrict__ hi, fp16* __restrict__ lo){
    int idx=blockIdx.x*blockDim.x+threadIdx.x; if (idx>=MPATCH*HID) return;
    int m=idx/HID, kk=idx%HID, b=m/(GP*GP), r=m%(GP*GP), i=r/GP, j=r%GP;
    int c=kk/(PSZ*PSZ), rem=kk%(PSZ*PSZ), p=rem/PSZ, q=rem%PSZ;
    float v=x[((size_t)(b*3+c)*IMG+(i*PSZ+p))*IMG+(j*PSZ+q)];
    fp16 h=__float2half(v);
    hi[idx]=h; lo[idx]=__float2half(v-__half2float(h));
}
__global__ void build_h(const float* __restrict__ xe, const float* __restrict__ cls,
                        const float* __restrict__ pos, float* __restrict__ h){
    int idx=blockIdx.x*blockDim.x+threadIdx.x; if (idx>=MTOK*HID) return;
    int m=idx/HID, d=idx%HID, b=m/SEQ, s=m%SEQ;
    float pv=pos[s*HID+d];
    h[idx] = (s==0)? cls[d]+pv : xe[(size_t)(b*(GP*GP)+(s-1))*HID+d]+pv;
}
__global__ void layernorm_k(const float* __restrict__ x, const float* __restrict__ sc,
                            const float* __restrict__ bi, fp16* __restrict__ oh, fp16* __restrict__ ol){
    int m=blockIdx.x, tid=threadIdx.x;
    const float* row=x+(size_t)m*HID;
    float v0=row[tid], v1=row[tid+256], v2=row[tid+512];
    __shared__ float red[256];
    red[tid]=v0+v1+v2; __syncthreads();
    #pragma unroll
    for (int o=128;o>0;o>>=1){ if(tid<o) red[tid]+=red[tid+o]; __syncthreads(); }
    float mu=red[0]*(1.0f/768.0f); __syncthreads();
    float d0=v0-mu,d1=v1-mu,d2=v2-mu;
    red[tid]=d0*d0+d1*d1+d2*d2; __syncthreads();
    #pragma unroll
    for (int o=128;o>0;o>>=1){ if(tid<o) red[tid]+=red[tid+o]; __syncthreads(); }
    float rs=rsqrtf(red[0]*(1.0f/768.0f)+1e-5f);
    size_t base=(size_t)m*HID;
    #pragma unroll
    for (int j=0;j<3;j++){
        int col=tid+j*256;
        float dd=(j==0)?d0:(j==1)?d1:d2;
        float v=dd*rs*sc[col]+bi[col];
        fp16 h=__float2half(v);
        oh[base+col]=h; ol[base+col]=__float2half(v-__half2float(h));
    }
}

// ---- attention (fp32, fused qkv input, fp16-split output) ----
#define ATT_SMEMF (197*65*2 + 8*200 + 8*64)
__global__ __launch_bounds__(256) void attention_k(const float* __restrict__ qkv, fp16* __restrict__ oh, fp16* __restrict__ ol){
    extern __shared__ float s[];
    float* Kh=s; float* Vh=s+197*65; float* sr=Vh+197*65; float* qr=sr+8*200;
    int bh=blockIdx.x, b=bh/NH, h=bh%NH;
    int tid=threadIdx.x, wid=tid>>5, lane=tid&31;
    const float* kb=qkv+(size_t)(b*SEQ)*QKVW+HID+h*DH;
    const float* vb=qkv+(size_t)(b*SEQ)*QKVW+2*HID+h*DH;
    for (int idx=tid; idx<SEQ*DH; idx+=256){
        int t=idx>>6, dk=idx&63;
        Kh[t*65+dk]=kb[(size_t)t*QKVW+dk];
        Vh[t*65+dk]=vb[(size_t)t*QKVW+dk];
    }
    __syncthreads();
    const float* qb=qkv+(size_t)(b*SEQ)*QKVW+h*DH;
    size_t ob=(size_t)(b*SEQ)*HID+h*DH;
    float* myS=sr+wid*200; float* myQ=qr+wid*64;
    for (int sq=wid; sq<SEQ; sq+=8){
        myQ[lane]=qb[(size_t)sq*QKVW+lane];
        myQ[lane+32]=qb[(size_t)sq*QKVW+lane+32];
        __syncwarp();
        float scs[7], mx=-1e30f;
        #pragma unroll
        for (int i=0;i<7;i++){
            int t=lane+32*i; float d=-1e30f;
            if (t<SEQ){ d=0.f;
                #pragma unroll
                for (int dk=0;dk<64;dk++) d+=myQ[dk]*Kh[t*65+dk];
                d*=0.125f; }
            scs[i]=d; mx=fmaxf(mx,d);
        }
        #pragma unroll
        for (int o=16;o>0;o>>=1) mx=fmaxf(mx,__shfl_xor_sync(0xffffffffu,mx,o));
        float sum=0.f;
        #pragma unroll
        for (int i=0;i<7;i++){ int t=lane+32*i; float e=(t<SEQ)?expf(scs[i]-mx):0.f; scs[i]=e; sum+=e; }
        #pragma unroll
        for (int o=16;o>0;o>>=1) sum+=__shfl_xor_sync(0xffffffffu,sum,o);
        float inv=1.f/sum;
        #pragma unroll
        for (int i=0;i<7;i++){ int t=lane+32*i; if (t<SEQ) myS[t]=scs[i]*inv; }
        __syncwarp();
        float a0=0.f, a1=0.f;
        for (int t=0;t<SEQ;t++){ float p=myS[t]; a0+=p*Vh[t*65+lane]; a1+=p*Vh[t*65+lane+32]; }
        size_t o0=ob+(size_t)sq*HID+lane;
        fp16 h0=__float2half(a0), h1=__float2half(a1);
        oh[o0]=h0; oh[o0+32]=h1;
        ol[o0]=__float2half(a0-__half2float(h0));
        ol[o0+32]=__float2half(a1-__half2float(h1));
        __syncwarp();
    }
}

__global__ void head_k(const float* __restrict__ h, const float* __restrict__ W,
                       const float* __restrict__ bi, float* __restrict__ out){
    __shared__ float row[HID];
    int b=blockIdx.y, n=blockIdx.x*256+threadIdx.x;
    const float* hr=h+(size_t)(b*SEQ)*HID;
    for (int i=threadIdx.x;i<HID;i+=256) row[i]=hr[i];
    __syncthreads();
    if (n<NCLS){
        float acc=bi[n];
        for (int d=0;d<HID;d++) acc+=row[d]*W[(size_t)d*NCLS+n];
        out[(size_t)b*NCLS+n]=acc;
    }
}

template<typename T> static T* sym(const void* s){ void* p=nullptr; cudaGetSymbolAddress(&p,s); return (T*)p; }

extern "C" void kernel_launch(void* const* d_in, const int* in_sizes, int n_in, void* d_out, int out_size){
    const float *x=(const float*)d_in[0], *conv_w=(const float*)d_in[1], *conv_b=(const float*)d_in[2];
    const float *cls=(const float*)d_in[3], *pos=(const float*)d_in[4];
    const float *ln1_s=(const float*)d_in[5], *ln1_b=(const float*)d_in[6];
    const float *wq=(const float*)d_in[7], *bq=(const float*)d_in[8];
    const float *wk=(const float*)d_in[9], *bk=(const float*)d_in[10];
    const float *wv=(const float*)d_in[11], *bv=(const float*)d_in[12];
    const float *wo=(const float*)d_in[13], *bo=(const float*)d_in[14];
    const float *ln2_s=(const float*)d_in[15], *ln2_b=(const float*)d_in[16];
    const float *w1=(const float*)d_in[17], *b1=(const float*)d_in[18];
    const float *w2=(const float*)d_in[19], *b2=(const float*)d_in[20];
    const float *head_w=(const float*)d_in[21], *head_b=(const float*)d_in[22];
    float* out=(float*)d_out;

    float* h_  = sym<float>(g_h);
    float* qkv_= sym<float>(g_qkv);
    float* bq_ = sym<float>(g_bq);
    fp16 *hnh=sym<fp16>(g_hn_h), *hnl=sym<fp16>(g_hn_l);
    fp16 *ath=sym<fp16>(g_at_h), *atl=sym<fp16>(g_at_l);
    fp16 *m1h=sym<fp16>(g_m1_h), *m1l=sym<fp16>(g_m1_l);
    fp16 *xph=sym<fp16>(g_xp_h), *xpl=sym<fp16>(g_xp_l);
    fp16 *Wqh=sym<fp16>(g_Wq_h);
    fp16 *Woh=sym<fp16>(g_Wo_h);
    fp16 *W1h=sym<fp16>(g_W1_h);
    fp16 *W2h=sym<fp16>(g_W2_h);
    fp16 *Wph=sym<fp16>(g_Wp_h);

    cudaFuncSetAttribute(tc_gemm, cudaFuncAttributeMaxDynamicSharedMemorySize, GSMEM);
    cudaFuncSetAttribute(attention_k, cudaFuncAttributeMaxDynamicSharedMemorySize, ATT_SMEMF*(int)sizeof(float));

    dim3 tb(32,8);
    patchify<<<(MPATCH*HID+255)/256,256>>>(x, xph, xpl);
    convWP_k<<<(HID*HID+255)/256,256>>>(conv_w, Wph);
    cbias_k<<<(NLAYER*QKVW+255)/256,256>>>(bq,bk,bv,bq_);
    tc_gemm<<<dim3(HID/BN,(MPATCH+BM-1)/BM),NTHR,GSMEM>>>(xph,xpl,Wph,MPATCH,HID,HID,conv_b,nullptr,qkv_,nullptr,nullptr,0);
    convQKV_k<<<dim3(24,72,12),tb>>>(wq,wk,wv,Wqh);
    convT_k<<<dim3(24,24,12),tb>>>(wo, Woh, HID, HID);
    convT_k<<<dim3(96,24,12),tb>>>(w1, W1h, HID, INTER);
    convT_k<<<dim3(24,96,12),tb>>>(w2, W2h, INTER, HID);
    build_h<<<(MTOK*HID+255)/256,256>>>(qkv_, cls, pos, h_);

    const int MT=(MTOK+BM-1)/BM;
    for (int l=0;l<NLAYER;l++){
        layernorm_k<<<MTOK,256>>>(h_, ln1_s+l*HID, ln1_b+l*HID, hnh, hnl);
        tc_gemm<<<dim3(QKVW/BN,MT),NTHR,GSMEM>>>(hnh,hnl,Wqh+(size_t)l*QKVW*HID,MTOK,QKVW,HID,bq_+l*QKVW,nullptr,qkv_,nullptr,nullptr,0);
        attention_k<<<BATCH*NH,256,ATT_SMEMF*(int)sizeof(float)>>>(qkv_, ath, atl);
        tc_gemm<<<dim3(HID/BN,MT),NTHR,GSMEM>>>(ath,atl,Woh+(size_t)l*HID*HID,MTOK,HID,HID,bo+l*HID,h_,h_,nullptr,nullptr,0);
        layernorm_k<<<MTOK,256>>>(h_, ln2_s+l*HID, ln2_b+l*HID, hnh, hnl);
        tc_gemm<<<dim3(INTER/BN,MT),NTHR,GSMEM>>>(hnh,hnl,W1h+(size_t)l*INTER*HID,MTOK,INTER,HID,b1+l*INTER,nullptr,nullptr,m1h,m1l,1);
        tc_gemm<<<dim3(HID/BN,MT),NTHR,GSMEM>>>(m1h,m1l,W2h+(size_t)l*HID*INTER,MTOK,HID,INTER,b2+l*HID,h_,h_,nullptr,nullptr,0);
    }
    head_k<<<dim3((NCLS+255)/256,BATCH),256>>>(h_, head_w, head_b, out);
}

// round 10
// speedup vs baseline: 1.4642x; 1.3341x over previous
#include <cuda_runtime.h>
#include <cuda_fp16.h>
#include <math.h>
#include <stdint.h>

#define BATCH 32
#define SEQ   197
#define MTOK  (BATCH*SEQ)
#define HID   768
#define NH    12
#define DH    64
#define INTER 3072
#define NLAYER 12
#define NCLS  1000
#define GP    14
#define PSZ   16
#define IMG   224
#define MPATCH (BATCH*GP*GP)
#define QKVW  2304
typedef __half fp16;

__device__ float g_h  [MTOK*HID];
__device__ float g_qkv[MTOK*QKVW];
__device__ fp16 g_hn [MTOK*HID];
__device__ fp16 g_at [MTOK*HID];
__device__ fp16 g_m1 [MTOK*INTER];
__device__ fp16 g_xp [MPATCH*HID];
__device__ fp16 g_Wq_h[NLAYER*QKVW*HID];
__device__ fp16 g_Wo_h[NLAYER*HID*HID];
__device__ fp16 g_W1_h[NLAYER*INTER*HID];
__device__ fp16 g_W2_h[NLAYER*HID*INTER];
__device__ fp16 g_Wp_h[HID*HID];
__device__ float g_bq[NLAYER*QKVW];

__device__ __forceinline__ uint32_t smem_u32(const void* p){
    uint32_t a; asm("{ .reg .u64 t; cvta.to.shared.u64 t, %1; cvt.u32.u64 %0, t; }":"=r"(a):"l"(p)); return a;
}

#define LDM4(r, ad) asm volatile("ldmatrix.sync.aligned.m8n8.x4.shared.b16 {%0,%1,%2,%3}, [%4];" \
  : "=r"((r)[0]),"=r"((r)[1]),"=r"((r)[2]),"=r"((r)[3]) : "r"(ad))
#define MMA(d, a, b0, b1) asm volatile( \
  "mma.sync.aligned.m16n8k16.row.col.f32.f16.f16.f32 {%0,%1,%2,%3}, {%4,%5,%6,%7}, {%8,%9}, {%0,%1,%2,%3};" \
  : "+f"((d)[0]), "+f"((d)[1]), "+f"((d)[2]), "+f"((d)[3]) \
  : "r"((a)[0]), "r"((a)[1]), "r"((a)[2]), "r"((a)[3]), "r"(b0), "r"(b1))
__device__ __forceinline__ void cpa16(uint32_t dst, const void* src, bool pred){
    asm volatile("cp.async.cg.shared.global [%0], [%1], 16, %2;" :: "r"(dst), "l"(src), "r"(pred?16:0));
}
#define CPA_COMMIT() asm volatile("cp.async.commit_group;" ::: "memory")
#define CPA_WAIT1()  asm volatile("cp.async.wait_group 1;" ::: "memory")
#define CPA_WAIT0()  asm volatile("cp.async.wait_group 0;" ::: "memory")

// ---- fp16 single-MMA GEMM: C[M,N] = A[M,K] @ B[N,K]^T, fp32 accum ----
// 128x128 block tile, 8 warps (warp tile 32x64), BK=32, 3-stage cp.async.
#define BM 128
#define BN 128
#define BK 32
#define SSTR 16384          // per-stage: A 8K | B 8K
#define GSMEM 69632         // >= 3 stages (48K) and >= epilogue staging (67.6K)
#define NTHR 256

__device__ __forceinline__ void load_stage(
    uint32_t d, const fp16* __restrict__ A, const fp16* __restrict__ B,
    int M, int K, int m0, int n0, int k0, int tid)
{
    const int lc = tid & 3;
    #pragma unroll
    for (int p = 0; p < 2; p++) {
        const int lr = (tid >> 2) + p*64;
        const uint32_t sw = (uint32_t)(lr*64 + ((lc ^ ((lr>>1)&3))<<4));
        const bool aok = (m0 + lr) < M;
        cpa16(d + sw,        A + (size_t)(m0 + lr)*K + k0 + lc*8, aok);
        cpa16(d + 8192 + sw, B + (size_t)(n0 + lr)*K + k0 + lc*8, true);
    }
}

__global__ __launch_bounds__(NTHR,2) void tc_gemm(
    const fp16* __restrict__ A, const fp16* __restrict__ B,
    int M, int N, int K, const float* __restrict__ bias, const float* __restrict__ resid,
    float* __restrict__ Cf, fp16* __restrict__ Ch, int act)
{
    extern __shared__ char smc[];
    const uint32_t sb = smem_u32(smc);
    const int tid = threadIdx.x, wid = tid>>5, lane = tid&31;
    const int m0 = blockIdx.y*BM, n0 = blockIdx.x*BN;
    const int warp_m = wid & 3, warp_n = wid >> 2;   // 4 x 2 warp grid, tile 32x64

    const int nc = K / BK;
    #pragma unroll
    for (int s = 0; s < 2; s++) {
        load_stage(sb + s*SSTR, A, B, M, K, m0, n0, s*BK, tid);
        CPA_COMMIT();
    }

    float acc[2][8][4];
    #pragma unroll
    for (int i=0;i<2;i++)
        #pragma unroll
        for (int j=0;j<8;j++)
            #pragma unroll
            for (int t=0;t<4;t++) acc[i][j][t]=0.f;

    const int lrow8 = (lane&7) + ((lane>>3)&1)*8;
    const int lhalf = lane>>4;

    for (int c = 0; c < nc; c++) {
        const int sidx = c % 3;
        CPA_WAIT1();
        __syncthreads();
        if (c + 2 < nc) {
            load_stage(sb + ((c+2)%3)*SSTR, A, B, M, K, m0, n0, (c+2)*BK, tid);
            CPA_COMMIT();
        }
        const uint32_t sa = sb + sidx*SSTR;
        #pragma unroll
        for (int kk = 0; kk < 2; kk++) {
            const int c16 = kk*2 + lhalf;
            uint32_t ah[2][4];
            #pragma unroll
            for (int mt = 0; mt < 2; mt++) {
                int row = warp_m*32 + mt*16 + lrow8;
                LDM4(ah[mt], sa + (uint32_t)(row*64 + ((c16 ^ ((row>>1)&3))<<4)));
            }
            #pragma unroll
            for (int n4 = 0; n4 < 4; n4++) {
                int row = warp_n*64 + n4*16 + lrow8;
                uint32_t bh[4];
                LDM4(bh, sa + 8192 + (uint32_t)(row*64 + ((c16 ^ ((row>>1)&3))<<4)));
                #pragma unroll
                for (int mt = 0; mt < 2; mt++)
                    #pragma unroll
                    for (int od = 0; od < 2; od++)
                        MMA(acc[mt][n4*2+od], ah[mt], bh[od], bh[od+2]);
            }
        }
    }
    CPA_WAIT0();
    __syncthreads();

    // epilogue: acc -> smem (stride 132) -> coalesced global
    float* stg = (float*)smc;
    const int ST = 132;
    #pragma unroll
    for (int mt = 0; mt < 2; mt++)
        #pragma unroll
        for (int nt = 0; nt < 8; nt++)
            #pragma unroll
            for (int i = 0; i < 4; i++) {
                int row = warp_m*32 + mt*16 + (lane>>2) + (i>>1)*8;
                int col = warp_n*64 + nt*8 + 2*(lane&3) + (i&1);
                stg[row*ST + col] = acc[mt][nt][i];
            }
    __syncthreads();

    #pragma unroll
    for (int i = 0; i < 16; i++) {
        int g = tid + i*NTHR;           // 128 rows x 32 quads
        int r = g >> 5, q = g & 31;
        int gm = m0 + r;
        if (gm >= M) continue;
        int n = n0 + q*4;
        float v0 = stg[r*ST + q*4 + 0] + bias[n+0];
        float v1 = stg[r*ST + q*4 + 1] + bias[n+1];
        float v2 = stg[r*ST + q*4 + 2] + bias[n+2];
        float v3 = stg[r*ST + q*4 + 3] + bias[n+3];
        if (act) {
            v0 = 0.5f*v0*(1.0f+erff(v0*0.70710678118654752f));
            v1 = 0.5f*v1*(1.0f+erff(v1*0.70710678118654752f));
            v2 = 0.5f*v2*(1.0f+erff(v2*0.70710678118654752f));
            v3 = 0.5f*v3*(1.0f+erff(v3*0.70710678118654752f));
        }
        if (resid) {
            const float* rp = resid + (size_t)gm*N + n;
            v0 += rp[0]; v1 += rp[1]; v2 += rp[2]; v3 += rp[3];
        }
        if (Cf) {
            *(float4*)(Cf + (size_t)gm*N + n) = make_float4(v0,v1,v2,v3);
        } else {
            uint2 sh;
            sh.x=(uint32_t)__half_as_ushort(__float2half(v0))|((uint32_t)__half_as_ushort(__float2half(v1))<<16);
            sh.y=(uint32_t)__half_as_ushort(__float2half(v2))|((uint32_t)__half_as_ushort(__float2half(v3))<<16);
            *(uint2*)(Ch+(size_t)gm*N+n)=sh;
        }
    }
}

// ---- weight conversions (fp16) ----
__global__ void convT_k(const float* __restrict__ in, fp16* __restrict__ hi, int K, int N){
    __shared__ float t[32][33];
    int l=blockIdx.z; in+=(size_t)l*K*N; hi+=(size_t)l*N*K;
    int n0=blockIdx.x*32, k0=blockIdx.y*32, tx=threadIdx.x, ty=threadIdx.y;
    #pragma unroll
    for (int i=0;i<32;i+=8) t[ty+i][tx]=in[(size_t)(k0+ty+i)*N+n0+tx];
    __syncthreads();
    #pragma unroll
    for (int i=0;i<32;i+=8)
        hi[(size_t)(n0+ty+i)*K+k0+tx]=__float2half(t[tx][ty+i]);
}
__global__ void convQKV_k(const float* __restrict__ wq, const float* __restrict__ wk, const float* __restrict__ wv,
                          fp16* __restrict__ hi){
    __shared__ float t[32][33];
    int l=blockIdx.z, k0=blockIdx.x*32, n0=blockIdx.y*32;
    int sel=n0/HID, nn=n0%HID, hh=nn/DH, d0=nn%DH;
    const float* w=(sel==0)?wq:(sel==1)?wk:wv;
    const float* base=w+((size_t)l*NH+hh)*HID*DH;
    int tx=threadIdx.x, ty=threadIdx.y;
    #pragma unroll
    for (int i=0;i<32;i+=8) t[ty+i][tx]=base[(size_t)(k0+ty+i)*DH+d0+tx];
    __syncthreads();
    size_t ob=(size_t)l*QKVW+n0;
    #pragma unroll
    for (int i=0;i<32;i+=8)
        hi[(ob+ty+i)*HID+k0+tx]=__float2half(t[tx][ty+i]);
}
__global__ void convWP_k(const float* __restrict__ w, fp16* __restrict__ hi){
    int i=blockIdx.x*blockDim.x+threadIdx.x; if (i>=HID*HID) return;
    hi[i]=__float2half(w[i]);
}
__global__ void cbias_k(const float* __restrict__ bq, const float* __restrict__ bk, const float* __restrict__ bv, float* __restrict__ o){
    int i=blockIdx.x*blockDim.x+threadIdx.x; if (i>=NLAYER*QKVW) return;
    int l=i/QKVW, n=i%QKVW;
    o[i] = (n<HID)? bq[l*HID+n] : (n<2*HID)? bk[l*HID+n-HID] : bv[l*HID+n-2*HID];
}

// ---- elementwise kernels ----
__global__ void patchify(const float* __restrict__ x, fp16* __restrict__ hi){
    int idx=blockIdx.x*blockDim.x+threadIdx.x; if (idx>=MPATCH*HID) return;
    int m=idx/HID, kk=idx%HID, b=m/(GP*GP), r=m%(GP*GP), i=r/GP, j=r%GP;
    int c=kk/(PSZ*PSZ), rem=kk%(PSZ*PSZ), p=rem/PSZ, q=rem%PSZ;
    hi[idx]=__float2half(x[((size_t)(b*3+c)*IMG+(i*PSZ+p))*IMG+(j*PSZ+q)]);
}
__global__ void build_h(const float* __restrict__ xe, const float* __restrict__ cls,
                        const float* __restrict__ pos, float* __restrict__ h){
    int idx=blockIdx.x*blockDim.x+threadIdx.x; if (idx>=MTOK*HID) return;
    int m=idx/HID, d=idx%HID, b=m/SEQ, s=m%SEQ;
    float pv=pos[s*HID+d];
    h[idx] = (s==0)? cls[d]+pv : xe[(size_t)(b*(GP*GP)+(s-1))*HID+d]+pv;
}
__global__ void layernorm_k(const float* __restrict__ x, const float* __restrict__ sc,
                            const float* __restrict__ bi, fp16* __restrict__ oh){
    int m=blockIdx.x, tid=threadIdx.x;
    const float* row=x+(size_t)m*HID;
    float v0=row[tid], v1=row[tid+256], v2=row[tid+512];
    __shared__ float red[256];
    red[tid]=v0+v1+v2; __syncthreads();
    #pragma unroll
    for (int o=128;o>0;o>>=1){ if(tid<o) red[tid]+=red[tid+o]; __syncthreads(); }
    float mu=red[0]*(1.0f/768.0f); __syncthreads();
    float d0=v0-mu,d1=v1-mu,d2=v2-mu;
    red[tid]=d0*d0+d1*d1+d2*d2; __syncthreads();
    #pragma unroll
    for (int o=128;o>0;o>>=1){ if(tid<o) red[tid]+=red[tid+o]; __syncthreads(); }
    float rs=rsqrtf(red[0]*(1.0f/768.0f)+1e-5f);
    size_t base=(size_t)m*HID;
    #pragma unroll
    for (int j=0;j<3;j++){
        int col=tid+j*256;
        float dd=(j==0)?d0:(j==1)?d1:d2;
        oh[base+col]=__float2half(dd*rs*sc[col]+bi[col]);
    }
}

// ---- attention (fp32, fused qkv input, fp16 output) ----
#define ATT_SMEMF (197*65*2 + 8*200 + 8*64)
__global__ __launch_bounds__(256) void attention_k(const float* __restrict__ qkv, fp16* __restrict__ oh){
    extern __shared__ float s[];
    float* Kh=s; float* Vh=s+197*65; float* sr=Vh+197*65; float* qr=sr+8*200;
    int bh=blockIdx.x, b=bh/NH, h=bh%NH;
    int tid=threadIdx.x, wid=tid>>5, lane=tid&31;
    const float* kb=qkv+(size_t)(b*SEQ)*QKVW+HID+h*DH;
    const float* vb=qkv+(size_t)(b*SEQ)*QKVW+2*HID+h*DH;
    for (int idx=tid; idx<SEQ*DH; idx+=256){
        int t=idx>>6, dk=idx&63;
        Kh[t*65+dk]=kb[(size_t)t*QKVW+dk];
        Vh[t*65+dk]=vb[(size_t)t*QKVW+dk];
    }
    __syncthreads();
    const float* qb=qkv+(size_t)(b*SEQ)*QKVW+h*DH;
    size_t ob=(size_t)(b*SEQ)*HID+h*DH;
    float* myS=sr+wid*200; float* myQ=qr+wid*64;
    for (int sq=wid; sq<SEQ; sq+=8){
        myQ[lane]=qb[(size_t)sq*QKVW+lane];
        myQ[lane+32]=qb[(size_t)sq*QKVW+lane+32];
        __syncwarp();
        float scs[7], mx=-1e30f;
        #pragma unroll
        for (int i=0;i<7;i++){
            int t=lane+32*i; float d=-1e30f;
            if (t<SEQ){ d=0.f;
                #pragma unroll
                for (int dk=0;dk<64;dk++) d+=myQ[dk]*Kh[t*65+dk];
                d*=0.125f; }
            scs[i]=d; mx=fmaxf(mx,d);
        }
        #pragma unroll
        for (int o=16;o>0;o>>=1) mx=fmaxf(mx,__shfl_xor_sync(0xffffffffu,mx,o));
        float sum=0.f;
        #pragma unroll
        for (int i=0;i<7;i++){ int t=lane+32*i; float e=(t<SEQ)?expf(scs[i]-mx):0.f; scs[i]=e; sum+=e; }
        #pragma unroll
        for (int o=16;o>0;o>>=1) sum+=__shfl_xor_sync(0xffffffffu,sum,o);
        float inv=1.f/sum;
        #pragma unroll
        for (int i=0;i<7;i++){ int t=lane+32*i; if (t<SEQ) myS[t]=scs[i]*inv; }
        __syncwarp();
        float a0=0.f, a1=0.f;
        for (int t=0;t<SEQ;t++){ float p=myS[t]; a0+=p*Vh[t*65+lane]; a1+=p*Vh[t*65+lane+32]; }
        size_t o0=ob+(size_t)sq*HID+lane;
        oh[o0]=__float2half(a0);
        oh[o0+32]=__float2half(a1);
        __syncwarp();
    }
}

__global__ void head_k(const float* __restrict__ h, const float* __restrict__ W,
                       const float* __restrict__ bi, float* __restrict__ out){
    __shared__ float row[HID];
    int b=blockIdx.y, n=blockIdx.x*256+threadIdx.x;
    const float* hr=h+(size_t)(b*SEQ)*HID;
    for (int i=threadIdx.x;i<HID;i+=256) row[i]=hr[i];
    __syncthreads();
    if (n<NCLS){
        float acc=bi[n];
        for (int d=0;d<HID;d++) acc+=row[d]*W[(size_t)d*NCLS+n];
        out[(size_t)b*NCLS+n]=acc;
    }
}

template<typename T> static T* sym(const void* s){ void* p=nullptr; cudaGetSymbolAddress(&p,s); return (T*)p; }

extern "C" void kernel_launch(void* const* d_in, const int* in_sizes, int n_in, void* d_out, int out_size){
    const float *x=(const float*)d_in[0], *conv_w=(const float*)d_in[1], *conv_b=(const float*)d_in[2];
    const float *cls=(const float*)d_in[3], *pos=(const float*)d_in[4];
    const float *ln1_s=(const float*)d_in[5], *ln1_b=(const float*)d_in[6];
    const float *wq=(const float*)d_in[7], *bq=(const float*)d_in[8];
    const float *wk=(const float*)d_in[9], *bk=(const float*)d_in[10];
    const float *wv=(const float*)d_in[11], *bv=(const float*)d_in[12];
    const float *wo=(const float*)d_in[13], *bo=(const float*)d_in[14];
    const float *ln2_s=(const float*)d_in[15], *ln2_b=(const float*)d_in[16];
    const float *w1=(const float*)d_in[17], *b1=(const float*)d_in[18];
    const float *w2=(const float*)d_in[19], *b2=(const float*)d_in[20];
    const float *head_w=(const float*)d_in[21], *head_b=(const float*)d_in[22];
    float* out=(float*)d_out;

    float* h_  = sym<float>(g_h);
    float* qkv_= sym<float>(g_qkv);
    float* bq_ = sym<float>(g_bq);
    fp16 *hn_=sym<fp16>(g_hn);
    fp16 *at_=sym<fp16>(g_at);
    fp16 *m1_=sym<fp16>(g_m1);
    fp16 *xp_=sym<fp16>(g_xp);
    fp16 *Wqh=sym<fp16>(g_Wq_h);
    fp16 *Woh=sym<fp16>(g_Wo_h);
    fp16 *W1h=sym<fp16>(g_W1_h);
    fp16 *W2h=sym<fp16>(g_W2_h);
    fp16 *Wph=sym<fp16>(g_Wp_h);

    cudaFuncSetAttribute(tc_gemm, cudaFuncAttributeMaxDynamicSharedMemorySize, GSMEM);
    cudaFuncSetAttribute(attention_k, cudaFuncAttributeMaxDynamicSharedMemorySize, ATT_SMEMF*(int)sizeof(float));

    dim3 tb(32,8);
    patchify<<<(MPATCH*HID+255)/256,256>>>(x, xp_);
    convWP_k<<<(HID*HID+255)/256,256>>>(conv_w, Wph);
    cbias_k<<<(NLAYER*QKVW+255)/256,256>>>(bq,bk,bv,bq_);
    tc_gemm<<<dim3(HID/BN,(MPATCH+BM-1)/BM),NTHR,GSMEM>>>(xp_,Wph,MPATCH,HID,HID,conv_b,nullptr,qkv_,nullptr,0);
    convQKV_k<<<dim3(24,72,12),tb>>>(wq,wk,wv,Wqh);
    convT_k<<<dim3(24,24,12),tb>>>(wo, Woh, HID, HID);
    convT_k<<<dim3(96,24,12),tb>>>(w1, W1h, HID, INTER);
    convT_k<<<dim3(24,96,12),tb>>>(w2, W2h, INTER, HID);
    build_h<<<(MTOK*HID+255)/256,256>>>(qkv_, cls, pos, h_);

    const int MT=(MTOK+BM-1)/BM;
    for (int l=0;l<NLAYER;l++){
        layernorm_k<<<MTOK,256>>>(h_, ln1_s+l*HID, ln1_b+l*HID, hn_);
        tc_gemm<<<dim3(QKVW/BN,MT),NTHR,GSMEM>>>(hn_,Wqh+(size_t)l*QKVW*HID,MTOK,QKVW,HID,bq_+l*QKVW,nullptr,qkv_,nullptr,0);
        attention_k<<<BATCH*NH,256,ATT_SMEMF*(int)sizeof(float)>>>(qkv_, at_);
        tc_gemm<<<dim3(HID/BN,MT),NTHR,GSMEM>>>(at_,Woh+(size_t)l*HID*HID,MTOK,HID,HID,bo+l*HID,h_,h_,nullptr,0);
        layernorm_k<<<MTOK,256>>>(h_, ln2_s+l*HID, ln2_b+l*HID, hn_);
        tc_gemm<<<dim3(INTER/BN,MT),NTHR,GSMEM>>>(hn_,W1h+(size_t)l*INTER*HID,MTOK,INTER,HID,b1+l*INTER,nullptr,nullptr,m1_,1);
        tc_gemm<<<dim3(HID/BN,MT),NTHR,GSMEM>>>(m1_,W2h+(size_t)l*HID*INTER,MTOK,HID,INTER,b2+l*HID,h_,h_,nullptr,0);
    }
    head_k<<<dim3((NCLS+255)/256,BATCH),256>>>(h_, head_w, head_b, out);
}

// round 11
// speedup vs baseline: 1.4664x; 1.0015x over previous
#include <cuda_runtime.h>
#include <cuda_fp16.h>
#include <math.h>
#include <stdint.h>

#define BATCH 32
#define SEQ   197
#define MTOK  (BATCH*SEQ)
#define HID   768
#define NH    12
#define DH    64
#define INTER 3072
#define NLAYER 12
#define NCLS  1000
#define GP    14
#define PSZ   16
#define IMG   224
#define MPATCH (BATCH*GP*GP)
#define QKVW  2304
typedef __half fp16;

__device__ float g_h  [MTOK*HID];
__device__ float g_qkv[MTOK*QKVW];
__device__ fp16 g_hn [MTOK*HID];
__device__ fp16 g_at [MTOK*HID];
__device__ fp16 g_m1 [MTOK*INTER];
__device__ fp16 g_xp [MPATCH*HID];
__device__ fp16 g_Wq_h[NLAYER*QKVW*HID];
__device__ fp16 g_Wo_h[NLAYER*HID*HID];
__device__ fp16 g_W1_h[NLAYER*INTER*HID];
__device__ fp16 g_W2_h[NLAYER*HID*INTER];
__device__ fp16 g_Wp_h[HID*HID];
__device__ float g_bq[NLAYER*QKVW];

__device__ __forceinline__ uint32_t smem_u32(const void* p){
    uint32_t a; asm("{ .reg .u64 t; cvta.to.shared.u64 t, %1; cvt.u32.u64 %0, t; }":"=r"(a):"l"(p)); return a;
}

#define LDM4(r, ad) asm volatile("ldmatrix.sync.aligned.m8n8.x4.shared.b16 {%0,%1,%2,%3}, [%4];" \
  : "=r"((r)[0]),"=r"((r)[1]),"=r"((r)[2]),"=r"((r)[3]) : "r"(ad))
#define MMA(d, a, b0, b1) asm volatile( \
  "mma.sync.aligned.m16n8k16.row.col.f32.f16.f16.f32 {%0,%1,%2,%3}, {%4,%5,%6,%7}, {%8,%9}, {%0,%1,%2,%3};" \
  : "+f"((d)[0]), "+f"((d)[1]), "+f"((d)[2]), "+f"((d)[3]) \
  : "r"((a)[0]), "r"((a)[1]), "r"((a)[2]), "r"((a)[3]), "r"(b0), "r"(b1))
__device__ __forceinline__ void cpa16(uint32_t dst, const void* src, bool pred){
    asm volatile("cp.async.cg.shared.global [%0], [%1], 16, %2;" :: "r"(dst), "l"(src), "r"(pred?16:0));
}
#define CPA_COMMIT() asm volatile("cp.async.commit_group;" ::: "memory")
#define CPA_WAIT1()  asm volatile("cp.async.wait_group 1;" ::: "memory")
#define CPA_WAIT0()  asm volatile("cp.async.wait_group 0;" ::: "memory")

// ---- fp16 single-MMA GEMM: C[M,N] = A[M,K] @ B[N,K]^T, fp32 accum ----
// 128x128 block tile, 8 warps (warp tile 32x64), BK=32, 3-stage cp.async.
// Direct fragment->global epilogue (no smem staging).
#define BM 128
#define BN 128
#define BK 32
#define SSTR 16384          // per-stage: A 8K | B 8K
#define GSMEM 49152         // 3 stages
#define NTHR 256

__device__ __forceinline__ void load_stage(
    uint32_t d, const fp16* __restrict__ A, const fp16* __restrict__ B,
    int M, int K, int m0, int n0, int k0, int tid)
{
    const int lc = tid & 3;
    #pragma unroll
    for (int p = 0; p < 2; p++) {
        const int lr = (tid >> 2) + p*64;
        const uint32_t sw = (uint32_t)(lr*64 + ((lc ^ ((lr>>1)&3))<<4));
        const bool aok = (m0 + lr) < M;
        cpa16(d + sw,        A + (size_t)(m0 + lr)*K + k0 + lc*8, aok);
        cpa16(d + 8192 + sw, B + (size_t)(n0 + lr)*K + k0 + lc*8, true);
    }
}

__global__ __launch_bounds__(NTHR,2) void tc_gemm(
    const fp16* __restrict__ A, const fp16* __restrict__ B,
    int M, int N, int K, const float* __restrict__ bias, const float* __restrict__ resid,
    float* __restrict__ Cf, fp16* __restrict__ Ch, int act)
{
    extern __shared__ char smc[];
    const uint32_t sb = smem_u32(smc);
    const int tid = threadIdx.x, wid = tid>>5, lane = tid&31;
    const int m0 = blockIdx.y*BM, n0 = blockIdx.x*BN;
    const int warp_m = wid & 3, warp_n = wid >> 2;   // 4 x 2 warp grid, tile 32x64

    const int nc = K / BK;
    #pragma unroll
    for (int s = 0; s < 2; s++) {
        load_stage(sb + s*SSTR, A, B, M, K, m0, n0, s*BK, tid);
        CPA_COMMIT();
    }

    float acc[2][8][4];
    #pragma unroll
    for (int i=0;i<2;i++)
        #pragma unroll
        for (int j=0;j<8;j++)
            #pragma unroll
            for (int t=0;t<4;t++) acc[i][j][t]=0.f;

    const int lrow8 = (lane&7) + ((lane>>3)&1)*8;
    const int lhalf = lane>>4;

    for (int c = 0; c < nc; c++) {
        const int sidx = c % 3;
        if (c >= nc-1) { CPA_WAIT0(); } else { CPA_WAIT1(); }
        __syncthreads();
        if (c + 2 < nc) {
            load_stage(sb + ((c+2)%3)*SSTR, A, B, M, K, m0, n0, (c+2)*BK, tid);
            CPA_COMMIT();
        }
        const uint32_t sa = sb + sidx*SSTR;
        #pragma unroll
        for (int kk = 0; kk < 2; kk++) {
            const int c16 = kk*2 + lhalf;
            uint32_t ah[2][4];
            #pragma unroll
            for (int mt = 0; mt < 2; mt++) {
                int row = warp_m*32 + mt*16 + lrow8;
                LDM4(ah[mt], sa + (uint32_t)(row*64 + ((c16 ^ ((row>>1)&3))<<4)));
            }
            #pragma unroll
            for (int n4 = 0; n4 < 4; n4++) {
                int row = warp_n*64 + n4*16 + lrow8;
                uint32_t bh[4];
                LDM4(bh, sa + 8192 + (uint32_t)(row*64 + ((c16 ^ ((row>>1)&3))<<4)));
                #pragma unroll
                for (int mt = 0; mt < 2; mt++)
                    #pragma unroll
                    for (int od = 0; od < 2; od++)
                        MMA(acc[mt][n4*2+od], ah[mt], bh[od], bh[od+2]);
            }
        }
    }

    // ---- direct epilogue: fragments -> global (float2 / half2) ----
    #pragma unroll
    for (int nt = 0; nt < 8; nt++) {
        const int col = n0 + warp_n*64 + nt*8 + 2*(lane&3);
        const float b0v = bias[col], b1v = bias[col+1];
        #pragma unroll
        for (int mt = 0; mt < 2; mt++) {
            #pragma unroll
            for (int hf = 0; hf < 2; hf++) {
                const int gm = m0 + warp_m*32 + mt*16 + (lane>>2) + hf*8;
                if (gm >= M) continue;
                float v0 = acc[mt][nt][hf*2+0] + b0v;
                float v1 = acc[mt][nt][hf*2+1] + b1v;
                if (act) {
                    v0 = 0.5f*v0*(1.0f+erff(v0*0.70710678118654752f));
                    v1 = 0.5f*v1*(1.0f+erff(v1*0.70710678118654752f));
                }
                if (resid) {
                    float2 rp = *(const float2*)(resid + (size_t)gm*N + col);
                    v0 += rp.x; v1 += rp.y;
                }
                if (Cf) {
                    *(float2*)(Cf + (size_t)gm*N + col) = make_float2(v0, v1);
                } else {
                    uint32_t p = (uint32_t)__half_as_ushort(__float2half(v0))
                               | ((uint32_t)__half_as_ushort(__float2half(v1)) << 16);
                    *(uint32_t*)(Ch + (size_t)gm*N + col) = p;
                }
            }
        }
    }
}

// ---- weight conversions (fp16) ----
__global__ void convT_k(const float* __restrict__ in, fp16* __restrict__ hi, int K, int N){
    __shared__ float t[32][33];
    int l=blockIdx.z; in+=(size_t)l*K*N; hi+=(size_t)l*N*K;
    int n0=blockIdx.x*32, k0=blockIdx.y*32, tx=threadIdx.x, ty=threadIdx.y;
    #pragma unroll
    for (int i=0;i<32;i+=8) t[ty+i][tx]=in[(size_t)(k0+ty+i)*N+n0+tx];
    __syncthreads();
    #pragma unroll
    for (int i=0;i<32;i+=8)
        hi[(size_t)(n0+ty+i)*K+k0+tx]=__float2half(t[tx][ty+i]);
}
__global__ void convQKV_k(const float* __restrict__ wq, const float* __restrict__ wk, const float* __restrict__ wv,
                          fp16* __restrict__ hi){
    __shared__ float t[32][33];
    int l=blockIdx.z, k0=blockIdx.x*32, n0=blockIdx.y*32;
    int sel=n0/HID, nn=n0%HID, hh=nn/DH, d0=nn%DH;
    const float* w=(sel==0)?wq:(sel==1)?wk:wv;
    const float* base=w+((size_t)l*NH+hh)*HID*DH;
    int tx=threadIdx.x, ty=threadIdx.y;
    #pragma unroll
    for (int i=0;i<32;i+=8) t[ty+i][tx]=base[(size_t)(k0+ty+i)*DH+d0+tx];
    __syncthreads();
    size_t ob=(size_t)l*QKVW+n0;
    #pragma unroll
    for (int i=0;i<32;i+=8)
        hi[(ob+ty+i)*HID+k0+tx]=__float2half(t[tx][ty+i]);
}
__global__ void convWP_k(const float* __restrict__ w, fp16* __restrict__ hi){
    int i=blockIdx.x*blockDim.x+threadIdx.x; if (i>=HID*HID) return;
    hi[i]=__float2half(w[i]);
}
__global__ void cbias_k(const float* __restrict__ bq, const float* __restrict__ bk, const float* __restrict__ bv, float* __restrict__ o){
    int i=blockIdx.x*blockDim.x+threadIdx.x; if (i>=NLAYER*QKVW) return;
    int l=i/QKVW, n=i%QKVW;
    o[i] = (n<HID)? bq[l*HID+n] : (n<2*HID)? bk[l*HID+n-HID] : bv[l*HID+n-2*HID];
}

// ---- elementwise kernels ----
__global__ void patchify(const float* __restrict__ x, fp16* __restrict__ hi){
    int idx=blockIdx.x*blockDim.x+threadIdx.x; if (idx>=MPATCH*HID) return;
    int m=idx/HID, kk=idx%HID, b=m/(GP*GP), r=m%(GP*GP), i=r/GP, j=r%GP;
    int c=kk/(PSZ*PSZ), rem=kk%(PSZ*PSZ), p=rem/PSZ, q=rem%PSZ;
    hi[idx]=__float2half(x[((size_t)(b*3+c)*IMG+(i*PSZ+p))*IMG+(j*PSZ+q)]);
}
__global__ void build_h(const float* __restrict__ xe, const float* __restrict__ cls,
                        const float* __restrict__ pos, float* __restrict__ h){
    int idx=blockIdx.x*blockDim.x+threadIdx.x; if (idx>=MTOK*HID) return;
    int m=idx/HID, d=idx%HID, b=m/SEQ, s=m%SEQ;
    float pv=pos[s*HID+d];
    h[idx] = (s==0)? cls[d]+pv : xe[(size_t)(b*(GP*GP)+(s-1))*HID+d]+pv;
}
__global__ void layernorm_k(const float* __restrict__ x, const float* __restrict__ sc,
                            const float* __restrict__ bi, fp16* __restrict__ oh){
    int m=blockIdx.x, tid=threadIdx.x;
    const float* row=x+(size_t)m*HID;
    float v0=row[tid], v1=row[tid+256], v2=row[tid+512];
    __shared__ float red[256];
    red[tid]=v0+v1+v2; __syncthreads();
    #pragma unroll
    for (int o=128;o>0;o>>=1){ if(tid<o) red[tid]+=red[tid+o]; __syncthreads(); }
    float mu=red[0]*(1.0f/768.0f); __syncthreads();
    float d0=v0-mu,d1=v1-mu,d2=v2-mu;
    red[tid]=d0*d0+d1*d1+d2*d2; __syncthreads();
    #pragma unroll
    for (int o=128;o>0;o>>=1){ if(tid<o) red[tid]+=red[tid+o]; __syncthreads(); }
    float rs=rsqrtf(red[0]*(1.0f/768.0f)+1e-5f);
    size_t base=(size_t)m*HID;
    #pragma unroll
    for (int j=0;j<3;j++){
        int col=tid+j*256;
        float dd=(j==0)?d0:(j==1)?d1:d2;
        oh[base+col]=__float2half(dd*rs*sc[col]+bi[col]);
    }
}

// ---- attention (fp32, fused qkv input, fp16 output) ----
#define ATT_SMEMF (197*65*2 + 8*200 + 8*64)
__global__ __launch_bounds__(256) void attention_k(const float* __restrict__ qkv, fp16* __restrict__ oh){
    extern __shared__ float s[];
    float* Kh=s; float* Vh=s+197*65; float* sr=Vh+197*65; float* qr=sr+8*200;
    int bh=blockIdx.x, b=bh/NH, h=bh%NH;
    int tid=threadIdx.x, wid=tid>>5, lane=tid&31;
    const float* kb=qkv+(size_t)(b*SEQ)*QKVW+HID+h*DH;
    const float* vb=qkv+(size_t)(b*SEQ)*QKVW+2*HID+h*DH;
    for (int idx=tid; idx<SEQ*DH; idx+=256){
        int t=idx>>6, dk=idx&63;
        Kh[t*65+dk]=kb[(size_t)t*QKVW+dk];
        Vh[t*65+dk]=vb[(size_t)t*QKVW+dk];
    }
    __syncthreads();
    const float* qb=qkv+(size_t)(b*SEQ)*QKVW+h*DH;
    size_t ob=(size_t)(b*SEQ)*HID+h*DH;
    float* myS=sr+wid*200; float* myQ=qr+wid*64;
    for (int sq=wid; sq<SEQ; sq+=8){
        myQ[lane]=qb[(size_t)sq*QKVW+lane];
        myQ[lane+32]=qb[(size_t)sq*QKVW+lane+32];
        __syncwarp();
        float scs[7], mx=-1e30f;
        #pragma unroll
        for (int i=0;i<7;i++){
            int t=lane+32*i; float d=-1e30f;
            if (t<SEQ){ d=0.f;
                #pragma unroll
                for (int dk=0;dk<64;dk++) d+=myQ[dk]*Kh[t*65+dk];
                d*=0.125f; }
            scs[i]=d; mx=fmaxf(mx,d);
        }
        #pragma unroll
        for (int o=16;o>0;o>>=1) mx=fmaxf(mx,__shfl_xor_sync(0xffffffffu,mx,o));
        float sum=0.f;
        #pragma unroll
        for (int i=0;i<7;i++){ int t=lane+32*i; float e=(t<SEQ)?expf(scs[i]-mx):0.f; scs[i]=e; sum+=e; }
        #pragma unroll
        for (int o=16;o>0;o>>=1) sum+=__shfl_xor_sync(0xffffffffu,sum,o);
        float inv=1.f/sum;
        #pragma unroll
        for (int i=0;i<7;i++){ int t=lane+32*i; if (t<SEQ) myS[t]=scs[i]*inv; }
        __syncwarp();
        float a0=0.f, a1=0.f;
        for (int t=0;t<SEQ;t++){ float p=myS[t]; a0+=p*Vh[t*65+lane]; a1+=p*Vh[t*65+lane+32]; }
        size_t o0=ob+(size_t)sq*HID+lane;
        oh[o0]=__float2half(a0);
        oh[o0+32]=__float2half(a1);
        __syncwarp();
    }
}

__global__ void head_k(const float* __restrict__ h, const float* __restrict__ W,
                       const float* __restrict__ bi, float* __restrict__ out){
    __shared__ float row[HID];
    int b=blockIdx.y, n=blockIdx.x*256+threadIdx.x;
    const float* hr=h+(size_t)(b*SEQ)*HID;
    for (int i=threadIdx.x;i<HID;i+=256) row[i]=hr[i];
    __syncthreads();
    if (n<NCLS){
        float acc=bi[n];
        for (int d=0;d<HID;d++) acc+=row[d]*W[(size_t)d*NCLS+n];
        out[(size_t)b*NCLS+n]=acc;
    }
}

template<typename T> static T* sym(const void* s){ void* p=nullptr; cudaGetSymbolAddress(&p,s); return (T*)p; }

extern "C" void kernel_launch(void* const* d_in, const int* in_sizes, int n_in, void* d_out, int out_size){
    const float *x=(const float*)d_in[0], *conv_w=(const float*)d_in[1], *conv_b=(const float*)d_in[2];
    const float *cls=(const float*)d_in[3], *pos=(const float*)d_in[4];
    const float *ln1_s=(const float*)d_in[5], *ln1_b=(const float*)d_in[6];
    const float *wq=(const float*)d_in[7], *bq=(const float*)d_in[8];
    const float *wk=(const float*)d_in[9], *bk=(const float*)d_in[10];
    const float *wv=(const float*)d_in[11], *bv=(const float*)d_in[12];
    const float *wo=(const float*)d_in[13], *bo=(const float*)d_in[14];
    const float *ln2_s=(const float*)d_in[15], *ln2_b=(const float*)d_in[16];
    const float *w1=(const float*)d_in[17], *b1=(const float*)d_in[18];
    const float *w2=(const float*)d_in[19], *b2=(const float*)d_in[20];
    const float *head_w=(const float*)d_in[21], *head_b=(const float*)d_in[22];
    float* out=(float*)d_out;

    float* h_  = sym<float>(g_h);
    float* qkv_= sym<float>(g_qkv);
    float* bq_ = sym<float>(g_bq);
    fp16 *hn_=sym<fp16>(g_hn);
    fp16 *at_=sym<fp16>(g_at);
    fp16 *m1_=sym<fp16>(g_m1);
    fp16 *xp_=sym<fp16>(g_xp);
    fp16 *Wqh=sym<fp16>(g_Wq_h);
    fp16 *Woh=sym<fp16>(g_Wo_h);
    fp16 *W1h=sym<fp16>(g_W1_h);
    fp16 *W2h=sym<fp16>(g_W2_h);
    fp16 *Wph=sym<fp16>(g_Wp_h);

    cudaFuncSetAttribute(tc_gemm, cudaFuncAttributeMaxDynamicSharedMemorySize, GSMEM);
    cudaFuncSetAttribute(attention_k, cudaFuncAttributeMaxDynamicSharedMemorySize, ATT_SMEMF*(int)sizeof(float));

    dim3 tb(32,8);
    patchify<<<(MPATCH*HID+255)/256,256>>>(x, xp_);
    convWP_k<<<(HID*HID+255)/256,256>>>(conv_w, Wph);
    cbias_k<<<(NLAYER*QKVW+255)/256,256>>>(bq,bk,bv,bq_);
    tc_gemm<<<dim3(HID/BN,(MPATCH+BM-1)/BM),NTHR,GSMEM>>>(xp_,Wph,MPATCH,HID,HID,conv_b,nullptr,qkv_,nullptr,0);
    convQKV_k<<<dim3(24,72,12),tb>>>(wq,wk,wv,Wqh);
    convT_k<<<dim3(24,24,12),tb>>>(wo, Woh, HID, HID);
    convT_k<<<dim3(96,24,12),tb>>>(w1, W1h, HID, INTER);
    convT_k<<<dim3(24,96,12),tb>>>(w2, W2h, INTER, HID);
    build_h<<<(MTOK*HID+255)/256,256>>>(qkv_, cls, pos, h_);

    const int MT=(MTOK+BM-1)/BM;
    for (int l=0;l<NLAYER;l++){
        layernorm_k<<<MTOK,256>>>(h_, ln1_s+l*HID, ln1_b+l*HID, hn_);
        tc_gemm<<<dim3(QKVW/BN,MT),NTHR,GSMEM>>>(hn_,Wqh+(size_t)l*QKVW*HID,MTOK,QKVW,HID,bq_+l*QKVW,nullptr,qkv_,nullptr,0);
        attention_k<<<BATCH*NH,256,ATT_SMEMF*(int)sizeof(float)>>>(qkv_, at_);
        tc_gemm<<<dim3(HID/BN,MT),NTHR,GSMEM>>>(at_,Woh+(size_t)l*HID*HID,MTOK,HID,HID,bo+l*HID,h_,h_,nullptr,0);
        layernorm_k<<<MTOK,256>>>(h_, ln2_s+l*HID, ln2_b+l*HID, hn_);
        tc_gemm<<<dim3(INTER/BN,MT),NTHR,GSMEM>>>(hn_,W1h+(size_t)l*INTER*HID,MTOK,INTER,HID,b1+l*INTER,nullptr,nullptr,m1_,1);
        tc_gemm<<<dim3(HID/BN,MT),NTHR,GSMEM>>>(m1_,W2h+(size_t)l*HID*INTER,MTOK,HID,INTER,b2+l*HID,h_,h_,nullptr,0);
    }
    head_k<<<dim3((NCLS+255)/256,BATCH),256>>>(h_, head_w, head_b, out);
}

// round 12
// speedup vs baseline: 1.6399x; 1.1183x over previous
#include <cuda_runtime.h>
#include <cuda_fp16.h>
#include <math.h>
#include <stdint.h>

#define BATCH 32
#define SEQ   197
#define MTOK  (BATCH*SEQ)
#define HID   768
#define NH    12
#define DH    64
#define INTER 3072
#define NLAYER 12
#define NCLS  1000
#define GP    14
#define PSZ   16
#define IMG   224
#define MPATCH (BATCH*GP*GP)
#define QKVW  2304
typedef __half fp16;

__device__ float g_h  [MTOK*HID];
__device__ float g_qkv[MTOK*QKVW];          // fp32, patch-embed staging only
__device__ fp16 g_qkvh[MTOK*QKVW];          // fp16 per-layer qkv
__device__ fp16 g_hn [MTOK*HID];
__device__ fp16 g_at [MTOK*HID];
__device__ fp16 g_m1 [MTOK*INTER];
__device__ fp16 g_xp [MPATCH*HID];
__device__ fp16 g_Wq_h[NLAYER*QKVW*HID];
__device__ fp16 g_Wo_h[NLAYER*HID*HID];
__device__ fp16 g_W1_h[NLAYER*INTER*HID];
__device__ fp16 g_W2_h[NLAYER*HID*INTER];
__device__ fp16 g_Wp_h[HID*HID];
__device__ float g_bq[NLAYER*QKVW];

__device__ __forceinline__ uint32_t smem_u32(const void* p){
    uint32_t a; asm("{ .reg .u64 t; cvta.to.shared.u64 t, %1; cvt.u32.u64 %0, t; }":"=r"(a):"l"(p)); return a;
}

#define LDM4(r, ad) asm volatile("ldmatrix.sync.aligned.m8n8.x4.shared.b16 {%0,%1,%2,%3}, [%4];" \
  : "=r"((r)[0]),"=r"((r)[1]),"=r"((r)[2]),"=r"((r)[3]) : "r"(ad))
#define MMA(d, a, b0, b1) asm volatile( \
  "mma.sync.aligned.m16n8k16.row.col.f32.f16.f16.f32 {%0,%1,%2,%3}, {%4,%5,%6,%7}, {%8,%9}, {%0,%1,%2,%3};" \
  : "+f"((d)[0]), "+f"((d)[1]), "+f"((d)[2]), "+f"((d)[3]) \
  : "r"((a)[0]), "r"((a)[1]), "r"((a)[2]), "r"((a)[3]), "r"(b0), "r"(b1))
__device__ __forceinline__ void cpa16(uint32_t dst, const void* src, bool pred){
    asm volatile("cp.async.cg.shared.global [%0], [%1], 16, %2;" :: "r"(dst), "l"(src), "r"(pred?16:0));
}
#define CPA_COMMIT() asm volatile("cp.async.commit_group;" ::: "memory")
#define CPA_WAIT1()  asm volatile("cp.async.wait_group 1;" ::: "memory")
#define CPA_WAIT0()  asm volatile("cp.async.wait_group 0;" ::: "memory")

// ---- fp16 single-MMA GEMM: C[M,N] = A[M,K] @ B[N,K]^T, fp32 accum ----
#define BM 128
#define BN 128
#define BK 32
#define SSTR 16384
#define GSMEM 49152
#define NTHR 256

__device__ __forceinline__ void load_stage(
    uint32_t d, const fp16* __restrict__ A, const fp16* __restrict__ B,
    int M, int K, int m0, int n0, int k0, int tid)
{
    const int lc = tid & 3;
    #pragma unroll
    for (int p = 0; p < 2; p++) {
        const int lr = (tid >> 2) + p*64;
        const uint32_t sw = (uint32_t)(lr*64 + ((lc ^ ((lr>>1)&3))<<4));
        const bool aok = (m0 + lr) < M;
        cpa16(d + sw,        A + (size_t)(m0 + lr)*K + k0 + lc*8, aok);
        cpa16(d + 8192 + sw, B + (size_t)(n0 + lr)*K + k0 + lc*8, true);
    }
}

__global__ __launch_bounds__(NTHR,2) void tc_gemm(
    const fp16* __restrict__ A, const fp16* __restrict__ B,
    int M, int N, int K, const float* __restrict__ bias, const float* __restrict__ resid,
    float* __restrict__ Cf, fp16* __restrict__ Ch, int act)
{
    extern __shared__ char smc[];
    const uint32_t sb = smem_u32(smc);
    const int tid = threadIdx.x, wid = tid>>5, lane = tid&31;
    const int m0 = blockIdx.y*BM, n0 = blockIdx.x*BN;
    const int warp_m = wid & 3, warp_n = wid >> 2;

    const int nc = K / BK;
    #pragma unroll
    for (int s = 0; s < 2; s++) {
        load_stage(sb + s*SSTR, A, B, M, K, m0, n0, s*BK, tid);
        CPA_COMMIT();
    }

    float acc[2][8][4];
    #pragma unroll
    for (int i=0;i<2;i++)
        #pragma unroll
        for (int j=0;j<8;j++)
            #pragma unroll
            for (int t=0;t<4;t++) acc[i][j][t]=0.f;

    const int lrow8 = (lane&7) + ((lane>>3)&1)*8;
    const int lhalf = lane>>4;

    for (int c = 0; c < nc; c++) {
        const int sidx = c % 3;
        if (c >= nc-1) { CPA_WAIT0(); } else { CPA_WAIT1(); }
        __syncthreads();
        if (c + 2 < nc) {
            load_stage(sb + ((c+2)%3)*SSTR, A, B, M, K, m0, n0, (c+2)*BK, tid);
            CPA_COMMIT();
        }
        const uint32_t sa = sb + sidx*SSTR;
        #pragma unroll
        for (int kk = 0; kk < 2; kk++) {
            const int c16 = kk*2 + lhalf;
            uint32_t ah[2][4];
            #pragma unroll
            for (int mt = 0; mt < 2; mt++) {
                int row = warp_m*32 + mt*16 + lrow8;
                LDM4(ah[mt], sa + (uint32_t)(row*64 + ((c16 ^ ((row>>1)&3))<<4)));
            }
            #pragma unroll
            for (int n4 = 0; n4 < 4; n4++) {
                int row = warp_n*64 + n4*16 + lrow8;
                uint32_t bh[4];
                LDM4(bh, sa + 8192 + (uint32_t)(row*64 + ((c16 ^ ((row>>1)&3))<<4)));
                #pragma unroll
                for (int mt = 0; mt < 2; mt++)
                    #pragma unroll
                    for (int od = 0; od < 2; od++)
                        MMA(acc[mt][n4*2+od], ah[mt], bh[od], bh[od+2]);
            }
        }
    }

    // ---- direct epilogue ----
    #pragma unroll
    for (int nt = 0; nt < 8; nt++) {
        const int col = n0 + warp_n*64 + nt*8 + 2*(lane&3);
        const float b0v = bias[col], b1v = bias[col+1];
        #pragma unroll
        for (int mt = 0; mt < 2; mt++) {
            #pragma unroll
            for (int hf = 0; hf < 2; hf++) {
                const int gm = m0 + warp_m*32 + mt*16 + (lane>>2) + hf*8;
                if (gm >= M) continue;
                float v0 = acc[mt][nt][hf*2+0] + b0v;
                float v1 = acc[mt][nt][hf*2+1] + b1v;
                if (act) {
                    v0 = 0.5f*v0*(1.0f+erff(v0*0.70710678118654752f));
                    v1 = 0.5f*v1*(1.0f+erff(v1*0.70710678118654752f));
                }
                if (resid) {
                    float2 rp = *(const float2*)(resid + (size_t)gm*N + col);
                    v0 += rp.x; v1 += rp.y;
                }
                if (Cf) {
                    *(float2*)(Cf + (size_t)gm*N + col) = make_float2(v0, v1);
                } else {
                    uint32_t p = (uint32_t)__half_as_ushort(__float2half(v0))
                               | ((uint32_t)__half_as_ushort(__float2half(v1)) << 16);
                    *(uint32_t*)(Ch + (size_t)gm*N + col) = p;
                }
            }
        }
    }
}

// ---- weight conversions ----
__global__ void convT_k(const float* __restrict__ in, fp16* __restrict__ hi, int K, int N){
    __shared__ float t[32][33];
    int l=blockIdx.z; in+=(size_t)l*K*N; hi+=(size_t)l*N*K;
    int n0=blockIdx.x*32, k0=blockIdx.y*32, tx=threadIdx.x, ty=threadIdx.y;
    #pragma unroll
    for (int i=0;i<32;i+=8) t[ty+i][tx]=in[(size_t)(k0+ty+i)*N+n0+tx];
    __syncthreads();
    #pragma unroll
    for (int i=0;i<32;i+=8)
        hi[(size_t)(n0+ty+i)*K+k0+tx]=__float2half(t[tx][ty+i]);
}
__global__ void convQKV_k(const float* __restrict__ wq, const float* __restrict__ wk, const float* __restrict__ wv,
                          fp16* __restrict__ hi){
    __shared__ float t[32][33];
    int l=blockIdx.z, k0=blockIdx.x*32, n0=blockIdx.y*32;
    int sel=n0/HID, nn=n0%HID, hh=nn/DH, d0=nn%DH;
    const float* w=(sel==0)?wq:(sel==1)?wk:wv;
    const float* base=w+((size_t)l*NH+hh)*HID*DH;
    int tx=threadIdx.x, ty=threadIdx.y;
    #pragma unroll
    for (int i=0;i<32;i+=8) t[ty+i][tx]=base[(size_t)(k0+ty+i)*DH+d0+tx];
    __syncthreads();
    size_t ob=(size_t)l*QKVW+n0;
    #pragma unroll
    for (int i=0;i<32;i+=8)
        hi[(ob+ty+i)*HID+k0+tx]=__float2half(t[tx][ty+i]);
}
__global__ void convWP_k(const float* __restrict__ w, fp16* __restrict__ hi){
    int i=blockIdx.x*blockDim.x+threadIdx.x; if (i>=HID*HID) return;
    hi[i]=__float2half(w[i]);
}
__global__ void cbias_k(const float* __restrict__ bq, const float* __restrict__ bk, const float* __restrict__ bv, float* __restrict__ o){
    int i=blockIdx.x*blockDim.x+threadIdx.x; if (i>=NLAYER*QKVW) return;
    int l=i/QKVW, n=i%QKVW;
    o[i] = (n<HID)? bq[l*HID+n] : (n<2*HID)? bk[l*HID+n-HID] : bv[l*HID+n-2*HID];
}

// ---- elementwise kernels ----
__global__ void patchify(const float* __restrict__ x, fp16* __restrict__ hi){
    int idx=blockIdx.x*blockDim.x+threadIdx.x; if (idx>=MPATCH*HID) return;
    int m=idx/HID, kk=idx%HID, b=m/(GP*GP), r=m%(GP*GP), i=r/GP, j=r%GP;
    int c=kk/(PSZ*PSZ), rem=kk%(PSZ*PSZ), p=rem/PSZ, q=rem%PSZ;
    hi[idx]=__float2half(x[((size_t)(b*3+c)*IMG+(i*PSZ+p))*IMG+(j*PSZ+q)]);
}
__global__ void build_h(const float* __restrict__ xe, const float* __restrict__ cls,
                        const float* __restrict__ pos, float* __restrict__ h){
    int idx=blockIdx.x*blockDim.x+threadIdx.x; if (idx>=MTOK*HID) return;
    int m=idx/HID, d=idx%HID, b=m/SEQ, s=m%SEQ;
    float pv=pos[s*HID+d];
    h[idx] = (s==0)? cls[d]+pv : xe[(size_t)(b*(GP*GP)+(s-1))*HID+d]+pv;
}
__global__ void layernorm_k(const float* __restrict__ x, const float* __restrict__ sc,
                            const float* __restrict__ bi, fp16* __restrict__ oh){
    int m=blockIdx.x, tid=threadIdx.x;
    const float* row=x+(size_t)m*HID;
    float v0=row[tid], v1=row[tid+256], v2=row[tid+512];
    __shared__ float red[256];
    red[tid]=v0+v1+v2; __syncthreads();
    #pragma unroll
    for (int o=128;o>0;o>>=1){ if(tid<o) red[tid]+=red[tid+o]; __syncthreads(); }
    float mu=red[0]*(1.0f/768.0f); __syncthreads();
    float d0=v0-mu,d1=v1-mu,d2=v2-mu;
    red[tid]=d0*d0+d1*d1+d2*d2; __syncthreads();
    #pragma unroll
    for (int o=128;o>0;o>>=1){ if(tid<o) red[tid]+=red[tid+o]; __syncthreads(); }
    float rs=rsqrtf(red[0]*(1.0f/768.0f)+1e-5f);
    size_t base=(size_t)m*HID;
    #pragma unroll
    for (int j=0;j<3;j++){
        int col=tid+j*256;
        float dd=(j==0)?d0:(j==1)?d1:d2;
        oh[base+col]=__float2half(dd*rs*sc[col]+bi[col]);
    }
}

// ---- attention: fp16 qkv input, half2 K/V smem (stride-33 words), fp16 out ----
#define ATT_SMEMW (197*33*2 + 8*200 + 8*64)   // uint32 words
__global__ __launch_bounds__(256) void attention_k(const fp16* __restrict__ qkv, fp16* __restrict__ oh){
    extern __shared__ uint32_t sw[];
    uint32_t* Kh2 = sw;
    uint32_t* Vh2 = sw + 197*33;
    float* sr = (float*)(sw + 2*197*33);
    float* qr = sr + 8*200;
    int bh=blockIdx.x, b=bh/NH, h=bh%NH;
    int tid=threadIdx.x, wid=tid>>5, lane=tid&31;
    const uint32_t* kb=(const uint32_t*)(qkv+(size_t)(b*SEQ)*QKVW+HID+h*DH);
    const uint32_t* vb=(const uint32_t*)(qkv+(size_t)(b*SEQ)*QKVW+2*HID+h*DH);
    for (int idx=tid; idx<SEQ*32; idx+=256){
        int t=idx>>5, dk2=idx&31;
        Kh2[t*33+dk2]=kb[(size_t)t*(QKVW/2)+dk2];
        Vh2[t*33+dk2]=vb[(size_t)t*(QKVW/2)+dk2];
    }
    __syncthreads();
    const fp16* qb=qkv+(size_t)(b*SEQ)*QKVW+h*DH;
    size_t ob=(size_t)(b*SEQ)*HID+h*DH;
    float* myS=sr+wid*200; float* myQ=qr+wid*64;
    for (int sq=wid; sq<SEQ; sq+=8){
        myQ[lane]=__half2float(qb[(size_t)sq*QKVW+lane]);
        myQ[lane+32]=__half2float(qb[(size_t)sq*QKVW+lane+32]);
        __syncwarp();
        float scs[7], mx=-1e30f;
        #pragma unroll
        for (int i=0;i<7;i++){
            int t=lane+32*i; float d=-1e30f;
            if (t<SEQ){
                d=0.f;
                #pragma unroll
                for (int dk2=0; dk2<32; dk2++){
                    __half2 kv = *(__half2*)&Kh2[t*33+dk2];
                    float2 kf = __half22float2(kv);
                    d += myQ[2*dk2]*kf.x + myQ[2*dk2+1]*kf.y;
                }
                d*=0.125f;
            }
            scs[i]=d; mx=fmaxf(mx,d);
        }
        #pragma unroll
        for (int o=16;o>0;o>>=1) mx=fmaxf(mx,__shfl_xor_sync(0xffffffffu,mx,o));
        float sum=0.f;
        #pragma unroll
        for (int i=0;i<7;i++){ int t=lane+32*i; float e=(t<SEQ)?expf(scs[i]-mx):0.f; scs[i]=e; sum+=e; }
        #pragma unroll
        for (int o=16;o>0;o>>=1) sum+=__shfl_xor_sync(0xffffffffu,sum,o);
        float inv=1.f/sum;
        #pragma unroll
        for (int i=0;i<7;i++){ int t=lane+32*i; if (t<SEQ) myS[t]=scs[i]*inv; }
        __syncwarp();
        float a0=0.f, a1=0.f;
        for (int t=0;t<SEQ;t++){
            float p=myS[t];
            __half2 v = *(__half2*)&Vh2[t*33+lane];
            float2 vf = __half22float2(v);
            a0 += p*vf.x; a1 += p*vf.y;
        }
        uint32_t pk = (uint32_t)__half_as_ushort(__float2half(a0))
                    | ((uint32_t)__half_as_ushort(__float2half(a1)) << 16);
        *(uint32_t*)(oh + ob + (size_t)sq*HID + 2*lane) = pk;
        __syncwarp();
    }
}

__global__ void head_k(const float* __restrict__ h, const float* __restrict__ W,
                       const float* __restrict__ bi, float* __restrict__ out){
    __shared__ float row[HID];
    int b=blockIdx.y, n=blockIdx.x*256+threadIdx.x;
    const float* hr=h+(size_t)(b*SEQ)*HID;
    for (int i=threadIdx.x;i<HID;i+=256) row[i]=hr[i];
    __syncthreads();
    if (n<NCLS){
        float acc=bi[n];
        for (int d=0;d<HID;d++) acc+=row[d]*W[(size_t)d*NCLS+n];
        out[(size_t)b*NCLS+n]=acc;
    }
}

template<typename T> static T* sym(const void* s){ void* p=nullptr; cudaGetSymbolAddress(&p,s); return (T*)p; }

extern "C" void kernel_launch(void* const* d_in, const int* in_sizes, int n_in, void* d_out, int out_size){
    const float *x=(const float*)d_in[0], *conv_w=(const float*)d_in[1], *conv_b=(const float*)d_in[2];
    const float *cls=(const float*)d_in[3], *pos=(const float*)d_in[4];
    const float *ln1_s=(const float*)d_in[5], *ln1_b=(const float*)d_in[6];
    const float *wq=(const float*)d_in[7], *bq=(const float*)d_in[8];
    const float *wk=(const float*)d_in[9], *bk=(const float*)d_in[10];
    const float *wv=(const float*)d_in[11], *bv=(const float*)d_in[12];
    const float *wo=(const float*)d_in[13], *bo=(const float*)d_in[14];
    const float *ln2_s=(const float*)d_in[15], *ln2_b=(const float*)d_in[16];
    const float *w1=(const float*)d_in[17], *b1=(const float*)d_in[18];
    const float *w2=(const float*)d_in[19], *b2=(const float*)d_in[20];
    const float *head_w=(const float*)d_in[21], *head_b=(const float*)d_in[22];
    float* out=(float*)d_out;

    float* h_  = sym<float>(g_h);
    float* qkv_= sym<float>(g_qkv);
    float* bq_ = sym<float>(g_bq);
    fp16 *qkvh=sym<fp16>(g_qkvh);
    fp16 *hn_=sym<fp16>(g_hn);
    fp16 *at_=sym<fp16>(g_at);
    fp16 *m1_=sym<fp16>(g_m1);
    fp16 *xp_=sym<fp16>(g_xp);
    fp16 *Wqh=sym<fp16>(g_Wq_h);
    fp16 *Woh=sym<fp16>(g_Wo_h);
    fp16 *W1h=sym<fp16>(g_W1_h);
    fp16 *W2h=sym<fp16>(g_W2_h);
    fp16 *Wph=sym<fp16>(g_Wp_h);

    cudaFuncSetAttribute(tc_gemm, cudaFuncAttributeMaxDynamicSharedMemorySize, GSMEM);
    cudaFuncSetAttribute(attention_k, cudaFuncAttributeMaxDynamicSharedMemorySize, ATT_SMEMW*(int)sizeof(uint32_t));

    dim3 tb(32,8);
    patchify<<<(MPATCH*HID+255)/256,256>>>(x, xp_);
    convWP_k<<<(HID*HID+255)/256,256>>>(conv_w, Wph);
    cbias_k<<<(NLAYER*QKVW+255)/256,256>>>(bq,bk,bv,bq_);
    tc_gemm<<<dim3(HID/BN,(MPATCH+BM-1)/BM),NTHR,GSMEM>>>(xp_,Wph,MPATCH,HID,HID,conv_b,nullptr,qkv_,nullptr,0);
    convQKV_k<<<dim3(24,72,12),tb>>>(wq,wk,wv,Wqh);
    convT_k<<<dim3(24,24,12),tb>>>(wo, Woh, HID, HID);
    convT_k<<<dim3(96,24,12),tb>>>(w1, W1h, HID, INTER);
    convT_k<<<dim3(24,96,12),tb>>>(w2, W2h, INTER, HID);
    build_h<<<(MTOK*HID+255)/256,256>>>(qkv_, cls, pos, h_);

    const int MT=(MTOK+BM-1)/BM;
    for (int l=0;l<NLAYER;l++){
        layernorm_k<<<MTOK,256>>>(h_, ln1_s+l*HID, ln1_b+l*HID, hn_);
        tc_gemm<<<dim3(QKVW/BN,MT),NTHR,GSMEM>>>(hn_,Wqh+(size_t)l*QKVW*HID,MTOK,QKVW,HID,bq_+l*QKVW,nullptr,nullptr,qkvh,0);
        attention_k<<<BATCH*NH,256,ATT_SMEMW*(int)sizeof(uint32_t)>>>(qkvh, at_);
        tc_gemm<<<dim3(HID/BN,MT),NTHR,GSMEM>>>(at_,Woh+(size_t)l*HID*HID,MTOK,HID,HID,bo+l*HID,h_,h_,nullptr,0);
        layernorm_k<<<MTOK,256>>>(h_, ln2_s+l*HID, ln2_b+l*HID, hn_);
        tc_gemm<<<dim3(INTER/BN,MT),NTHR,GSMEM>>>(hn_,W1h+(size_t)l*INTER*HID,MTOK,INTER,HID,b1+l*INTER,nullptr,nullptr,m1_,1);
        tc_gemm<<<dim3(HID/BN,MT),NTHR,GSMEM>>>(m1_,W2h+(size_t)l*HID*INTER,MTOK,HID,INTER,b2+l*HID,h_,h_,nullptr,0);
    }
    head_k<<<dim3((NCLS+255)/256,BATCH),256>>>(h_, head_w, head_b, out);
}

// round 13
// speedup vs baseline: 1.7956x; 1.0950x over previous
#include <cuda_runtime.h>
#include <cuda_fp16.h>
#include <math.h>
#include <stdint.h>

#define BATCH 32
#define SEQ   197
#define MTOK  (BATCH*SEQ)
#define HID   768
#define NH    12
#define DH    64
#define INTER 3072
#define NLAYER 12
#define NCLS  1000
#define GP    14
#define PSZ   16
#define IMG   224
#define MPATCH (BATCH*GP*GP)
#define QKVW  2304
typedef __half fp16;

__device__ float g_h  [MTOK*HID];
__device__ float g_qkv[MTOK*QKVW];          // fp32, patch-embed staging only
__device__ fp16 g_qkvh[MTOK*QKVW];          // fp16 per-layer qkv
__device__ fp16 g_hn [MTOK*HID];
__device__ fp16 g_at [MTOK*HID];
__device__ fp16 g_m1 [MTOK*INTER];
__device__ fp16 g_xp [MPATCH*HID];
__device__ fp16 g_Wq_h[NLAYER*QKVW*HID];
__device__ fp16 g_Wo_h[NLAYER*HID*HID];
__device__ fp16 g_W1_h[NLAYER*INTER*HID];
__device__ fp16 g_W2_h[NLAYER*HID*INTER];
__device__ fp16 g_Wp_h[HID*HID];
__device__ float g_bq[NLAYER*QKVW];

__device__ __forceinline__ uint32_t smem_u32(const void* p){
    uint32_t a; asm("{ .reg .u64 t; cvta.to.shared.u64 t, %1; cvt.u32.u64 %0, t; }":"=r"(a):"l"(p)); return a;
}

#define LDM4(r, ad) asm volatile("ldmatrix.sync.aligned.m8n8.x4.shared.b16 {%0,%1,%2,%3}, [%4];" \
  : "=r"((r)[0]),"=r"((r)[1]),"=r"((r)[2]),"=r"((r)[3]) : "r"(ad))
#define MMA(d, a, b0, b1) asm volatile( \
  "mma.sync.aligned.m16n8k16.row.col.f32.f16.f16.f32 {%0,%1,%2,%3}, {%4,%5,%6,%7}, {%8,%9}, {%0,%1,%2,%3};" \
  : "+f"((d)[0]), "+f"((d)[1]), "+f"((d)[2]), "+f"((d)[3]) \
  : "r"((a)[0]), "r"((a)[1]), "r"((a)[2]), "r"((a)[3]), "r"(b0), "r"(b1))
__device__ __forceinline__ void cpa16(uint32_t dst, const void* src, bool pred){
    asm volatile("cp.async.cg.shared.global [%0], [%1], 16, %2;" :: "r"(dst), "l"(src), "r"(pred?16:0));
}
#define CPA_COMMIT() asm volatile("cp.async.commit_group;" ::: "memory")
#define CPA_WAIT1()  asm volatile("cp.async.wait_group 1;" ::: "memory")
#define CPA_WAIT0()  asm volatile("cp.async.wait_group 0;" ::: "memory")

// ---- fp16 single-MMA GEMM: C[M,N] = A[M,K] @ B[N,K]^T, fp32 accum ----
// 128x128 block tile, 8 warps (warp tile 32x64), BK=64 (128B rows), 3-stage cp.async.
#define BM 128
#define BN 128
#define BK 64
#define SSTR 32768          // per-stage: A 16K | B 16K
#define GSMEM 98304         // 3 stages
#define NTHR 256

__device__ __forceinline__ void load_stage(
    uint32_t d, const fp16* __restrict__ A, const fp16* __restrict__ B,
    int M, int K, int m0, int n0, int k0, int tid)
{
    const int lc = tid & 7;                      // 8 x 16B chunks per 128B row
    #pragma unroll
    for (int p = 0; p < 4; p++) {
        const int lr = (tid >> 3) + p*32;        // rows 0..127
        const uint32_t sw = (uint32_t)(lr*128 + ((lc ^ (lr&7))<<4));
        const bool aok = (m0 + lr) < M;
        cpa16(d + sw,         A + (size_t)(m0 + lr)*K + k0 + lc*8, aok);
        cpa16(d + 16384 + sw, B + (size_t)(n0 + lr)*K + k0 + lc*8, true);
    }
}

__global__ __launch_bounds__(NTHR,2) void tc_gemm(
    const fp16* __restrict__ A, const fp16* __restrict__ B,
    int M, int N, int K, const float* __restrict__ bias, const float* __restrict__ resid,
    float* __restrict__ Cf, fp16* __restrict__ Ch, int act)
{
    extern __shared__ char smc[];
    const uint32_t sb = smem_u32(smc);
    const int tid = threadIdx.x, wid = tid>>5, lane = tid&31;
    const int m0 = blockIdx.y*BM, n0 = blockIdx.x*BN;
    const int warp_m = wid & 3, warp_n = wid >> 2;

    const int nc = K / BK;
    #pragma unroll
    for (int s = 0; s < 2; s++) {
        load_stage(sb + s*SSTR, A, B, M, K, m0, n0, s*BK, tid);
        CPA_COMMIT();
    }

    float acc[2][8][4];
    #pragma unroll
    for (int i=0;i<2;i++)
        #pragma unroll
        for (int j=0;j<8;j++)
            #pragma unroll
            for (int t=0;t<4;t++) acc[i][j][t]=0.f;

    const int lrow8 = (lane&7) + ((lane>>3)&1)*8;
    const int lhalf = lane>>4;

    for (int c = 0; c < nc; c++) {
        const int sidx = c % 3;
        if (c >= nc-1) { CPA_WAIT0(); } else { CPA_WAIT1(); }
        __syncthreads();
        if (c + 2 < nc) {
            load_stage(sb + ((c+2)%3)*SSTR, A, B, M, K, m0, n0, (c+2)*BK, tid);
            CPA_COMMIT();
        }
        const uint32_t sa = sb + sidx*SSTR;
        #pragma unroll
        for (int kk = 0; kk < 4; kk++) {
            const int c16 = kk*2 + lhalf;        // 0..7
            uint32_t ah[2][4];
            #pragma unroll
            for (int mt = 0; mt < 2; mt++) {
                int row = warp_m*32 + mt*16 + lrow8;
                LDM4(ah[mt], sa + (uint32_t)(row*128 + ((c16 ^ (row&7))<<4)));
            }
            #pragma unroll
            for (int n4 = 0; n4 < 4; n4++) {
                int row = warp_n*64 + n4*16 + lrow8;
                uint32_t bh[4];
                LDM4(bh, sa + 16384 + (uint32_t)(row*128 + ((c16 ^ (row&7))<<4)));
                #pragma unroll
                for (int mt = 0; mt < 2; mt++)
                    #pragma unroll
                    for (int od = 0; od < 2; od++)
                        MMA(acc[mt][n4*2+od], ah[mt], bh[od], bh[od+2]);
            }
        }
    }

    // ---- direct epilogue ----
    #pragma unroll
    for (int nt = 0; nt < 8; nt++) {
        const int col = n0 + warp_n*64 + nt*8 + 2*(lane&3);
        const float b0v = bias[col], b1v = bias[col+1];
        #pragma unroll
        for (int mt = 0; mt < 2; mt++) {
            #pragma unroll
            for (int hf = 0; hf < 2; hf++) {
                const int gm = m0 + warp_m*32 + mt*16 + (lane>>2) + hf*8;
                if (gm >= M) continue;
                float v0 = acc[mt][nt][hf*2+0] + b0v;
                float v1 = acc[mt][nt][hf*2+1] + b1v;
                if (act) {
                    v0 = 0.5f*v0*(1.0f+erff(v0*0.70710678118654752f));
                    v1 = 0.5f*v1*(1.0f+erff(v1*0.70710678118654752f));
                }
                if (resid) {
                    float2 rp = *(const float2*)(resid + (size_t)gm*N + col);
                    v0 += rp.x; v1 += rp.y;
                }
                if (Cf) {
                    *(float2*)(Cf + (size_t)gm*N + col) = make_float2(v0, v1);
                } else {
                    uint32_t p = (uint32_t)__half_as_ushort(__float2half(v0))
                               | ((uint32_t)__half_as_ushort(__float2half(v1)) << 16);
                    *(uint32_t*)(Ch + (size_t)gm*N + col) = p;
                }
            }
        }
    }
}

// ---- weight conversions ----
__global__ void convT_k(const float* __restrict__ in, fp16* __restrict__ hi, int K, int N){
    __shared__ float t[32][33];
    int l=blockIdx.z; in+=(size_t)l*K*N; hi+=(size_t)l*N*K;
    int n0=blockIdx.x*32, k0=blockIdx.y*32, tx=threadIdx.x, ty=threadIdx.y;
    #pragma unroll
    for (int i=0;i<32;i+=8) t[ty+i][tx]=in[(size_t)(k0+ty+i)*N+n0+tx];
    __syncthreads();
    #pragma unroll
    for (int i=0;i<32;i+=8)
        hi[(size_t)(n0+ty+i)*K+k0+tx]=__float2half(t[tx][ty+i]);
}
__global__ void convQKV_k(const float* __restrict__ wq, const float* __restrict__ wk, const float* __restrict__ wv,
                          fp16* __restrict__ hi){
    __shared__ float t[32][33];
    int l=blockIdx.z, k0=blockIdx.x*32, n0=blockIdx.y*32;
    int sel=n0/HID, nn=n0%HID, hh=nn/DH, d0=nn%DH;
    const float* w=(sel==0)?wq:(sel==1)?wk:wv;
    const float* base=w+((size_t)l*NH+hh)*HID*DH;
    int tx=threadIdx.x, ty=threadIdx.y;
    #pragma unroll
    for (int i=0;i<32;i+=8) t[ty+i][tx]=base[(size_t)(k0+ty+i)*DH+d0+tx];
    __syncthreads();
    size_t ob=(size_t)l*QKVW+n0;
    #pragma unroll
    for (int i=0;i<32;i+=8)
        hi[(ob+ty+i)*HID+k0+tx]=__float2half(t[tx][ty+i]);
}
__global__ void convWP_k(const float* __restrict__ w, fp16* __restrict__ hi){
    int i=blockIdx.x*blockDim.x+threadIdx.x; if (i>=HID*HID) return;
    hi[i]=__float2half(w[i]);
}
__global__ void cbias_k(const float* __restrict__ bq, const float* __restrict__ bk, const float* __restrict__ bv, float* __restrict__ o){
    int i=blockIdx.x*blockDim.x+threadIdx.x; if (i>=NLAYER*QKVW) return;
    int l=i/QKVW, n=i%QKVW;
    o[i] = (n<HID)? bq[l*HID+n] : (n<2*HID)? bk[l*HID+n-HID] : bv[l*HID+n-2*HID];
}

// ---- elementwise kernels ----
__global__ void patchify(const float* __restrict__ x, fp16* __restrict__ hi){
    int idx=blockIdx.x*blockDim.x+threadIdx.x; if (idx>=MPATCH*HID) return;
    int m=idx/HID, kk=idx%HID, b=m/(GP*GP), r=m%(GP*GP), i=r/GP, j=r%GP;
    int c=kk/(PSZ*PSZ), rem=kk%(PSZ*PSZ), p=rem/PSZ, q=rem%PSZ;
    hi[idx]=__float2half(x[((size_t)(b*3+c)*IMG+(i*PSZ+p))*IMG+(j*PSZ+q)]);
}
__global__ void build_h(const float* __restrict__ xe, const float* __restrict__ cls,
                        const float* __restrict__ pos, float* __restrict__ h){
    int idx=blockIdx.x*blockDim.x+threadIdx.x; if (idx>=MTOK*HID) return;
    int m=idx/HID, d=idx%HID, b=m/SEQ, s=m%SEQ;
    float pv=pos[s*HID+d];
    h[idx] = (s==0)? cls[d]+pv : xe[(size_t)(b*(GP*GP)+(s-1))*HID+d]+pv;
}
// warp-shuffle single-pass LN (sum + sumsq), 1 barrier
__global__ void layernorm_k(const float* __restrict__ x, const float* __restrict__ sc,
                            const float* __restrict__ bi, fp16* __restrict__ oh){
    int m=blockIdx.x, tid=threadIdx.x, lane=tid&31, wid=tid>>5;
    const float* row=x+(size_t)m*HID;
    float v0=row[tid], v1=row[tid+256], v2=row[tid+512];
    float s=v0+v1+v2;
    float q=v0*v0+v1*v1+v2*v2;
    #pragma unroll
    for (int o=16;o>0;o>>=1){
        s+=__shfl_xor_sync(0xffffffffu,s,o);
        q+=__shfl_xor_sync(0xffffffffu,q,o);
    }
    __shared__ float ws[8], wq[8];
    if (lane==0){ ws[wid]=s; wq[wid]=q; }
    __syncthreads();
    float st=0.f, qt=0.f;
    #pragma unroll
    for (int i=0;i<8;i++){ st+=ws[i]; qt+=wq[i]; }
    float mu=st*(1.0f/768.0f);
    float var=qt*(1.0f/768.0f)-mu*mu;
    float rs=rsqrtf(var+1e-5f);
    size_t base=(size_t)m*HID;
    oh[base+tid]     = __float2half((v0-mu)*rs*sc[tid]     + bi[tid]);
    oh[base+tid+256] = __float2half((v1-mu)*rs*sc[tid+256] + bi[tid+256]);
    oh[base+tid+512] = __float2half((v2-mu)*rs*sc[tid+512] + bi[tid+512]);
}

// ---- attention: fp16 qkv input, half2 K/V smem (stride-33 words), fp16 out ----
#define ATT_SMEMW (197*33*2 + 8*200 + 8*64)   // uint32 words
__global__ __launch_bounds__(256) void attention_k(const fp16* __restrict__ qkv, fp16* __restrict__ oh){
    extern __shared__ uint32_t sw[];
    uint32_t* Kh2 = sw;
    uint32_t* Vh2 = sw + 197*33;
    float* sr = (float*)(sw + 2*197*33);
    float* qr = sr + 8*200;
    int bh=blockIdx.x, b=bh/NH, h=bh%NH;
    int tid=threadIdx.x, wid=tid>>5, lane=tid&31;
    const uint32_t* kb=(const uint32_t*)(qkv+(size_t)(b*SEQ)*QKVW+HID+h*DH);
    const uint32_t* vb=(const uint32_t*)(qkv+(size_t)(b*SEQ)*QKVW+2*HID+h*DH);
    for (int idx=tid; idx<SEQ*32; idx+=256){
        int t=idx>>5, dk2=idx&31;
        Kh2[t*33+dk2]=kb[(size_t)t*(QKVW/2)+dk2];
        Vh2[t*33+dk2]=vb[(size_t)t*(QKVW/2)+dk2];
    }
    __syncthreads();
    const fp16* qb=qkv+(size_t)(b*SEQ)*QKVW+h*DH;
    size_t ob=(size_t)(b*SEQ)*HID+h*DH;
    float* myS=sr+wid*200; float* myQ=qr+wid*64;
    for (int sq=wid; sq<SEQ; sq+=8){
        myQ[lane]=__half2float(qb[(size_t)sq*QKVW+lane]);
        myQ[lane+32]=__half2float(qb[(size_t)sq*QKVW+lane+32]);
        __syncwarp();
        float scs[7], mx=-1e30f;
        #pragma unroll
        for (int i=0;i<7;i++){
            int t=lane+32*i; float d=-1e30f;
            if (t<SEQ){
                d=0.f;
                #pragma unroll
                for (int dk2=0; dk2<32; dk2++){
                    __half2 kv = *(__half2*)&Kh2[t*33+dk2];
                    float2 kf = __half22float2(kv);
                    d += myQ[2*dk2]*kf.x + myQ[2*dk2+1]*kf.y;
                }
                d*=0.125f;
            }
            scs[i]=d; mx=fmaxf(mx,d);
        }
        #pragma unroll
        for (int o=16;o>0;o>>=1) mx=fmaxf(mx,__shfl_xor_sync(0xffffffffu,mx,o));
        float sum=0.f;
        #pragma unroll
        for (int i=0;i<7;i++){ int t=lane+32*i; float e=(t<SEQ)?expf(scs[i]-mx):0.f; scs[i]=e; sum+=e; }
        #pragma unroll
        for (int o=16;o>0;o>>=1) sum+=__shfl_xor_sync(0xffffffffu,sum,o);
        float inv=1.f/sum;
        #pragma unroll
        for (int i=0;i<7;i++){ int t=lane+32*i; if (t<SEQ) myS[t]=scs[i]*inv; }
        __syncwarp();
        float a0=0.f, a1=0.f;
        for (int t=0;t<SEQ;t++){
            float p=myS[t];
            __half2 v = *(__half2*)&Vh2[t*33+lane];
            float2 vf = __half22float2(v);
            a0 += p*vf.x; a1 += p*vf.y;
        }
        uint32_t pk = (uint32_t)__half_as_ushort(__float2half(a0))
                    | ((uint32_t)__half_as_ushort(__float2half(a1)) << 16);
        *(uint32_t*)(oh + ob + (size_t)sq*HID + 2*lane) = pk;
        __syncwarp();
    }
}

__global__ void head_k(const float* __restrict__ h, const float* __restrict__ W,
                       const float* __restrict__ bi, float* __restrict__ out){
    __shared__ float row[HID];
    int b=blockIdx.y, n=blockIdx.x*256+threadIdx.x;
    const float* hr=h+(size_t)(b*SEQ)*HID;
    for (int i=threadIdx.x;i<HID;i+=256) row[i]=hr[i];
    __syncthreads();
    if (n<NCLS){
        float acc=bi[n];
        for (int d=0;d<HID;d++) acc+=row[d]*W[(size_t)d*NCLS+n];
        out[(size_t)b*NCLS+n]=acc;
    }
}

template<typename T> static T* sym(const void* s){ void* p=nullptr; cudaGetSymbolAddress(&p,s); return (T*)p; }

extern "C" void kernel_launch(void* const* d_in, const int* in_sizes, int n_in, void* d_out, int out_size){
    const float *x=(const float*)d_in[0], *conv_w=(const float*)d_in[1], *conv_b=(const float*)d_in[2];
    const float *cls=(const float*)d_in[3], *pos=(const float*)d_in[4];
    const float *ln1_s=(const float*)d_in[5], *ln1_b=(const float*)d_in[6];
    const float *wq=(const float*)d_in[7], *bq=(const float*)d_in[8];
    const float *wk=(const float*)d_in[9], *bk=(const float*)d_in[10];
    const float *wv=(const float*)d_in[11], *bv=(const float*)d_in[12];
    const float *wo=(const float*)d_in[13], *bo=(const float*)d_in[14];
    const float *ln2_s=(const float*)d_in[15], *ln2_b=(const float*)d_in[16];
    const float *w1=(const float*)d_in[17], *b1=(const float*)d_in[18];
    const float *w2=(const float*)d_in[19], *b2=(const float*)d_in[20];
    const float *head_w=(const float*)d_in[21], *head_b=(const float*)d_in[22];
    float* out=(float*)d_out;

    float* h_  = sym<float>(g_h);
    float* qkv_= sym<float>(g_qkv);
    float* bq_ = sym<float>(g_bq);
    fp16 *qkvh=sym<fp16>(g_qkvh);
    fp16 *hn_=sym<fp16>(g_hn);
    fp16 *at_=sym<fp16>(g_at);
    fp16 *m1_=sym<fp16>(g_m1);
    fp16 *xp_=sym<fp16>(g_xp);
    fp16 *Wqh=sym<fp16>(g_Wq_h);
    fp16 *Woh=sym<fp16>(g_Wo_h);
    fp16 *W1h=sym<fp16>(g_W1_h);
    fp16 *W2h=sym<fp16>(g_W2_h);
    fp16 *Wph=sym<fp16>(g_Wp_h);

    cudaFuncSetAttribute(tc_gemm, cudaFuncAttributeMaxDynamicSharedMemorySize, GSMEM);
    cudaFuncSetAttribute(attention_k, cudaFuncAttributeMaxDynamicSharedMemorySize, ATT_SMEMW*(int)sizeof(uint32_t));

    dim3 tb(32,8);
    patchify<<<(MPATCH*HID+255)/256,256>>>(x, xp_);
    convWP_k<<<(HID*HID+255)/256,256>>>(conv_w, Wph);
    cbias_k<<<(NLAYER*QKVW+255)/256,256>>>(bq,bk,bv,bq_);
    tc_gemm<<<dim3(HID/BN,(MPATCH+BM-1)/BM),NTHR,GSMEM>>>(xp_,Wph,MPATCH,HID,HID,conv_b,nullptr,qkv_,nullptr,0);
    convQKV_k<<<dim3(24,72,12),tb>>>(wq,wk,wv,Wqh);
    convT_k<<<dim3(24,24,12),tb>>>(wo, Woh, HID, HID);
    convT_k<<<dim3(96,24,12),tb>>>(w1, W1h, HID, INTER);
    convT_k<<<dim3(24,96,12),tb>>>(w2, W2h, INTER, HID);
    build_h<<<(MTOK*HID+255)/256,256>>>(qkv_, cls, pos, h_);

    const int MT=(MTOK+BM-1)/BM;
    for (int l=0;l<NLAYER;l++){
        layernorm_k<<<MTOK,256>>>(h_, ln1_s+l*HID, ln1_b+l*HID, hn_);
        tc_gemm<<<dim3(QKVW/BN,MT),NTHR,GSMEM>>>(hn_,Wqh+(size_t)l*QKVW*HID,MTOK,QKVW,HID,bq_+l*QKVW,nullptr,nullptr,qkvh,0);
        attention_k<<<BATCH*NH,256,ATT_SMEMW*(int)sizeof(uint32_t)>>>(qkvh, at_);
        tc_gemm<<<dim3(HID/BN,MT),NTHR,GSMEM>>>(at_,Woh+(size_t)l*HID*HID,MTOK,HID,HID,bo+l*HID,h_,h_,nullptr,0);
        layernorm_k<<<MTOK,256>>>(h_, ln2_s+l*HID, ln2_b+l*HID, hn_);
        tc_gemm<<<dim3(INTER/BN,MT),NTHR,GSMEM>>>(hn_,W1h+(size_t)l*INTER*HID,MTOK,INTER,HID,b1+l*INTER,nullptr,nullptr,m1_,1);
        tc_gemm<<<dim3(HID/BN,MT),NTHR,GSMEM>>>(m1_,W2h+(size_t)l*HID*INTER,MTOK,HID,INTER,b2+l*HID,h_,h_,nullptr,0);
    }
    head_k<<<dim3((NCLS+255)/256,BATCH),256>>>(h_, head_w, head_b, out);
}